// round 2
// baseline (speedup 1.0000x reference)
#include <cuda_runtime.h>
#include <cuda_bf16.h>
#include <math.h>

#define NB      4
#define TT      1024
#define DM      1024
#define NH      16
#define DH      64
#define RLEN    2047   // 2*T - 1

// ---------------- scratch (device globals; no allocation allowed) ----------
__device__ float g_Qu[(size_t)NB*NH*TT*DH];     // Q + u   (N,H,T,d)
__device__ float g_Qv[(size_t)NB*NH*TT*DH];     // Q + v   (N,H,T,d)
__device__ float g_K [(size_t)NB*NH*TT*DH];     // K       (N,H,T,d)
__device__ float g_V [(size_t)NB*NH*TT*DH];     // V       (N,H,T,d)
__device__ float g_R [(size_t)RLEN*DM];         // rel_pe @ Wr^T  (2T-1, D)
__device__ float g_S [(size_t)NB*NH*TT*TT];     // scores/attn (N,H,T,T)
__device__ float g_O [(size_t)NB*TT*DM];        // attn @ V, head-concat (N,T,D)

// ---------------------------------------------------------------------------
// Generic tiled SGEMM: C = A(MxK) @ B(1024xK)^T (+bias), K = 1024.
// MODE 0: flat C0[m*1024+n] (+bias if non-null)
// MODE 1: head layout C0[((nb*16+h)*1024+t)*64+dh] (+bias)
// MODE 2: head layout dual: C0 = .. + bias + u[n], C1 = .. + bias + v[n]
// BM=BN=64, BK=16, 256 threads, 4x4 per thread.
// ---------------------------------------------------------------------------
template<int MODE>
__global__ void sgemm_bt(const float* __restrict__ A, const float* __restrict__ B,
                         const float* __restrict__ bias,
                         float* __restrict__ C0, float* __restrict__ C1,
                         const float* __restrict__ u, const float* __restrict__ v,
                         int M)
{
    __shared__ float As[16][64];
    __shared__ float Bs[16][64];
    const int tx = threadIdx.x, ty = threadIdx.y;
    const int tid = ty * 16 + tx;
    const int m0 = blockIdx.x * 64, n0 = blockIdx.y * 64;

    float acc[4][4] = {};
    const int lr = tid >> 2;          // 0..63
    const int lc = (tid & 3) * 4;     // 0,4,8,12

    for (int k0 = 0; k0 < 1024; k0 += 16) {
        float4 av = make_float4(0.f, 0.f, 0.f, 0.f);
        const int gm = m0 + lr;
        if (gm < M) av = *(const float4*)(A + (size_t)gm * 1024 + k0 + lc);
        As[lc + 0][lr] = av.x; As[lc + 1][lr] = av.y;
        As[lc + 2][lr] = av.z; As[lc + 3][lr] = av.w;

        float4 bv = *(const float4*)(B + (size_t)(n0 + lr) * 1024 + k0 + lc);
        Bs[lc + 0][lr] = bv.x; Bs[lc + 1][lr] = bv.y;
        Bs[lc + 2][lr] = bv.z; Bs[lc + 3][lr] = bv.w;
        __syncthreads();

        #pragma unroll
        for (int kk = 0; kk < 16; kk++) {
            float ra[4], rb[4];
            #pragma unroll
            for (int i = 0; i < 4; i++) ra[i] = As[kk][ty + 16 * i];
            #pragma unroll
            for (int j = 0; j < 4; j++) rb[j] = Bs[kk][tx + 16 * j];
            #pragma unroll
            for (int i = 0; i < 4; i++)
                #pragma unroll
                for (int j = 0; j < 4; j++)
                    acc[i][j] = fmaf(ra[i], rb[j], acc[i][j]);
        }
        __syncthreads();
    }

    #pragma unroll
    for (int i = 0; i < 4; i++) {
        const int m = m0 + ty + 16 * i;
        if (m >= M) continue;
        #pragma unroll
        for (int j = 0; j < 4; j++) {
            const int n = n0 + tx + 16 * j;
            float val = acc[i][j];
            if (MODE == 0) {
                if (bias) val += bias[n];
                C0[(size_t)m * 1024 + n] = val;
            } else {
                val += bias[n];
                const int nb = m >> 10, t = m & 1023;
                const int h  = n >> 6,  dh = n & 63;
                const size_t idx = (((size_t)(nb * NH + h)) * TT + t) * DH + dh;
                if (MODE == 1) {
                    C0[idx] = val;
                } else {
                    C0[idx] = val + u[n];
                    C1[idx] = val + v[n];
                }
            }
        }
    }
}

// ---------------------------------------------------------------------------
// Fused score kernel with rel-shift folded in:
//   S[bh, i, j] = (Q_i+u)·K_j  +  (Q_i+v)·R[i - j + T - 1, head]
// 32x32 output tile per block, 256 threads, each thread 4 scores.
// ---------------------------------------------------------------------------
__global__ void score_kernel()
{
    __shared__ float Qus[32][65];
    __shared__ float Qvs[32][65];
    __shared__ float Ks [32][65];
    __shared__ float Rs [63][65];

    const int bh = blockIdx.z;          // n*16 + h
    const int h  = bh & 15;
    const int i0 = blockIdx.y * 32;
    const int j0 = blockIdx.x * 32;
    const int tid = threadIdx.x;        // 0..255

    const float* Qu = g_Qu + (size_t)bh * TT * DH;
    const float* Qv = g_Qv + (size_t)bh * TT * DH;
    const float* Kp = g_K  + (size_t)bh * TT * DH;

    // 32x64 tiles: 2048 floats = 8 per thread, coalesced
    #pragma unroll
    for (int q = 0; q < 8; q++) {
        const int f = tid + q * 256;
        const int r = f >> 6, c = f & 63;
        Qus[r][c] = Qu[(size_t)(i0 + r) * DH + c];
        Qvs[r][c] = Qv[(size_t)(i0 + r) * DH + c];
        Ks [r][c] = Kp[(size_t)(j0 + r) * DH + c];
    }
    // R diagonal band: rows rbase .. rbase+62, head slice [h*64 .. h*64+63]
    const int rbase = i0 - j0 + (TT - 1) - 31;   // always in [0, 2T-2-62]
    #pragma unroll
    for (int q = 0; q < 16; q++) {
        const int f = tid + q * 256;
        if (f < 63 * 64) {
            const int r = f >> 6, c = f & 63;
            Rs[r][c] = g_R[(size_t)(rbase + r) * DM + h * DH + c];
        }
    }
    __syncthreads();

    const int ti = tid >> 5;    // 0..7  (constant within a warp)
    const int tj = tid & 31;    // lane -> j_local

    float acc[4] = {0.f, 0.f, 0.f, 0.f};
    #pragma unroll 8
    for (int kk = 0; kk < 64; kk++) {
        const float kv = Ks[tj][kk];
        #pragma unroll
        for (int q = 0; q < 4; q++) {
            const int il = ti + 8 * q;
            acc[q] = fmaf(Qus[il][kk], kv, acc[q]);
            acc[q] = fmaf(Qvs[il][kk], Rs[il - tj + 31][kk], acc[q]);
        }
    }

    float* Sp = g_S + (size_t)bh * TT * TT;
    #pragma unroll
    for (int q = 0; q < 4; q++) {
        Sp[(size_t)(i0 + ti + 8 * q) * TT + j0 + tj] = acc[q];
    }
}

// ---------------------------------------------------------------------------
// Row softmax over S, with scale = d^-0.5 = 0.125 applied to logits.
// One block per row of 1024.
// ---------------------------------------------------------------------------
__global__ void softmax_kernel()
{
    const int row = blockIdx.x;
    float* p = g_S + (size_t)row * TT;
    const int tid = threadIdx.x;    // 256
    const float scale = 0.125f;

    float v[4];
    float m = -1e30f;
    #pragma unroll
    for (int q = 0; q < 4; q++) {
        v[q] = p[tid + q * 256] * scale;
        m = fmaxf(m, v[q]);
    }

    __shared__ float red[256];
    red[tid] = m;
    __syncthreads();
    for (int s = 128; s > 0; s >>= 1) {
        if (tid < s) red[tid] = fmaxf(red[tid], red[tid + s]);
        __syncthreads();
    }
    m = red[0];
    __syncthreads();

    float sum = 0.f;
    #pragma unroll
    for (int q = 0; q < 4; q++) {
        v[q] = expf(v[q] - m);
        sum += v[q];
    }
    red[tid] = sum;
    __syncthreads();
    for (int s = 128; s > 0; s >>= 1) {
        if (tid < s) red[tid] += red[tid + s];
        __syncthreads();
    }
    const float inv = 1.f / red[0];
    #pragma unroll
    for (int q = 0; q < 4; q++) {
        p[tid + q * 256] = v[q] * inv;
    }
}

// ---------------------------------------------------------------------------
// O = attn @ V per (n,h), written straight into (N, T, H*d) concat layout.
// BM=64 (t), BN=64 (=d), BK=16 over s=1024.
// ---------------------------------------------------------------------------
__global__ void av_kernel()
{
    __shared__ float As[16][64];
    __shared__ float Vs[16][64];

    const int bh = blockIdx.y;
    const int m0 = blockIdx.x * 64;
    const float* A  = g_S + (size_t)bh * TT * TT;
    const float* Vp = g_V + (size_t)bh * TT * DH;

    const int tx = threadIdx.x, ty = threadIdx.y;
    const int tid = ty * 16 + tx;

    float acc[4][4] = {};
    const int lr = tid >> 2, lc = (tid & 3) * 4;       // A loader
    const int vr = tid >> 4, vc = (tid & 15) * 4;      // V loader

    for (int k0 = 0; k0 < 1024; k0 += 16) {
        float4 av = *(const float4*)(A + (size_t)(m0 + lr) * TT + k0 + lc);
        As[lc + 0][lr] = av.x; As[lc + 1][lr] = av.y;
        As[lc + 2][lr] = av.z; As[lc + 3][lr] = av.w;

        *(float4*)&Vs[vr][vc] = *(const float4*)(Vp + (size_t)(k0 + vr) * DH + vc);
        __syncthreads();

        #pragma unroll
        for (int kk = 0; kk < 16; kk++) {
            float ra[4], rb[4];
            #pragma unroll
            for (int i = 0; i < 4; i++) ra[i] = As[kk][ty + 16 * i];
            #pragma unroll
            for (int j = 0; j < 4; j++) rb[j] = Vs[kk][tx + 16 * j];
            #pragma unroll
            for (int i = 0; i < 4; i++)
                #pragma unroll
                for (int j = 0; j < 4; j++)
                    acc[i][j] = fmaf(ra[i], rb[j], acc[i][j]);
        }
        __syncthreads();
    }

    const int nb = bh >> 4, h = bh & 15;
    #pragma unroll
    for (int i = 0; i < 4; i++) {
        const int t = m0 + ty + 16 * i;
        #pragma unroll
        for (int j = 0; j < 4; j++) {
            const int n = tx + 16 * j;
            g_O[((size_t)nb * TT + t) * DM + h * DH + n] = acc[i][j];
        }
    }
}

// ---------------------------------------------------------------------------
extern "C" void kernel_launch(void* const* d_in, const int* in_sizes, int n_in,
                              void* d_out, int out_size)
{
    (void)in_sizes; (void)n_in; (void)out_size;
    const float* x      = (const float*)d_in[0];
    const float* rel_pe = (const float*)d_in[1];
    const float* Wq     = (const float*)d_in[2];
    const float* bq     = (const float*)d_in[3];
    const float* Wk     = (const float*)d_in[4];
    const float* bk     = (const float*)d_in[5];
    const float* Wv     = (const float*)d_in[6];
    const float* bv     = (const float*)d_in[7];
    const float* Wo     = (const float*)d_in[8];
    const float* bo     = (const float*)d_in[9];
    const float* Wr     = (const float*)d_in[10];
    const float* u      = (const float*)d_in[11];
    const float* v      = (const float*)d_in[12];
    float* out = (float*)d_out;

    float *pQu, *pQv, *pK, *pV, *pR, *pO;
    cudaGetSymbolAddress((void**)&pQu, g_Qu);
    cudaGetSymbolAddress((void**)&pQv, g_Qv);
    cudaGetSymbolAddress((void**)&pK,  g_K);
    cudaGetSymbolAddress((void**)&pV,  g_V);
    cudaGetSymbolAddress((void**)&pR,  g_R);
    cudaGetSymbolAddress((void**)&pO,  g_O);

    const dim3 blk(16, 16);

    // Projections
    sgemm_bt<2><<<dim3(64, 16), blk>>>(x, Wq, bq, pQu, pQv, u, v, NB * TT);
    sgemm_bt<1><<<dim3(64, 16), blk>>>(x, Wk, bk, pK, nullptr, nullptr, nullptr, NB * TT);
    sgemm_bt<1><<<dim3(64, 16), blk>>>(x, Wv, bv, pV, nullptr, nullptr, nullptr, NB * TT);
    sgemm_bt<0><<<dim3(32, 16), blk>>>(rel_pe, Wr, nullptr, pR, nullptr, nullptr, nullptr, RLEN);

    // Fused AC + rel-shifted BD scores
    score_kernel<<<dim3(TT / 32, TT / 32, NB * NH), 256>>>();

    // Softmax
    softmax_kernel<<<NB * NH * TT, 256>>>();

    // attn @ V -> (N,T,D)
    av_kernel<<<dim3(TT / 64, NB * NH), blk>>>();

    // Output projection
    sgemm_bt<0><<<dim3(64, 16), blk>>>(pO, Wo, bo, out, nullptr, nullptr, nullptr, NB * TT);
}

// round 5
// speedup vs baseline: 1.7303x; 1.7303x over previous
#include <cuda_runtime.h>
#include <cuda_bf16.h>
#include <math.h>

#define NB      4
#define TT      1024
#define DM      1024
#define NH      16
#define DH      64
#define RLEN    2047   // 2*T - 1

// ---------------- scratch (device globals; no allocation allowed) ----------
__device__ float g_Qu[(size_t)NB*NH*TT*DH];     // Q + u   (N,H,T,d)
__device__ float g_Qv[(size_t)NB*NH*TT*DH];     // Q + v   (N,H,T,d)
__device__ float g_K [(size_t)NB*NH*TT*DH];     // K       (N,H,T,d)
__device__ float g_V [(size_t)NB*NH*TT*DH];     // V       (N,H,T,d)
__device__ float g_R [(size_t)RLEN*DM];         // rel_pe @ Wr^T  (2T-1, D)
__device__ float g_S [(size_t)NB*NH*TT*TT];     // scores/attn (N,H,T,T)
__device__ float g_O [(size_t)NB*TT*DM];        // attn @ V, head-concat (N,T,D)

// ---------------------------------------------------------------------------
// Tiled SGEMM: C = A(MxK) @ B(1024xK)^T (+bias), K = 1024.
// 128x128 block tile, 256 threads, 8x8 strided micro-tile.
// MODE 0: flat C0[m*1024+n] (+bias if non-null)
// MODE 1: head layout C0[((nb*16+h)*1024+t)*64+dh] (+bias)
// MODE 2: head layout dual: C0 = .. + bias + u[n], C1 = .. + bias + v[n]
// ---------------------------------------------------------------------------
template<int MODE>
__global__ __launch_bounds__(256) void sgemm_bt(
    const float* __restrict__ A, const float* __restrict__ B,
    const float* __restrict__ bias,
    float* __restrict__ C0, float* __restrict__ C1,
    const float* __restrict__ u, const float* __restrict__ v,
    int M)
{
    __shared__ float As[16][129];   // [k][m]
    __shared__ float Bs[16][129];   // [k][n]
    const int tid = threadIdx.x;
    const int tx = tid & 15, ty = tid >> 4;
    const int m0 = blockIdx.x * 128, n0 = blockIdx.y * 128;

    const int lrow = tid >> 2;          // 0..63
    const int lc4  = (tid & 3) * 4;     // 0,4,8,12

    float acc[8][8] = {};

    for (int k0 = 0; k0 < 1024; k0 += 16) {
        #pragma unroll
        for (int q = 0; q < 2; q++) {
            const int row = lrow + q * 64;
            const int gm = m0 + row;
            float4 av = make_float4(0.f, 0.f, 0.f, 0.f);
            if (gm < M) av = *(const float4*)(A + (size_t)gm * 1024 + k0 + lc4);
            As[lc4 + 0][row] = av.x; As[lc4 + 1][row] = av.y;
            As[lc4 + 2][row] = av.z; As[lc4 + 3][row] = av.w;

            float4 bv = *(const float4*)(B + (size_t)(n0 + row) * 1024 + k0 + lc4);
            Bs[lc4 + 0][row] = bv.x; Bs[lc4 + 1][row] = bv.y;
            Bs[lc4 + 2][row] = bv.z; Bs[lc4 + 3][row] = bv.w;
        }
        __syncthreads();

        #pragma unroll 4
        for (int kk = 0; kk < 16; kk++) {
            float ra[8], rb[8];
            #pragma unroll
            for (int ii = 0; ii < 8; ii++) ra[ii] = As[kk][ty + 16 * ii];
            #pragma unroll
            for (int jj = 0; jj < 8; jj++) rb[jj] = Bs[kk][tx + 16 * jj];
            #pragma unroll
            for (int ii = 0; ii < 8; ii++)
                #pragma unroll
                for (int jj = 0; jj < 8; jj++)
                    acc[ii][jj] = fmaf(ra[ii], rb[jj], acc[ii][jj]);
        }
        __syncthreads();
    }

    #pragma unroll
    for (int ii = 0; ii < 8; ii++) {
        const int m = m0 + ty + 16 * ii;
        if (m >= M) continue;
        #pragma unroll
        for (int jj = 0; jj < 8; jj++) {
            const int n = n0 + tx + 16 * jj;
            float val = acc[ii][jj];
            if (MODE == 0) {
                if (bias) val += bias[n];
                C0[(size_t)m * 1024 + n] = val;
            } else {
                val += bias[n];
                const int nb = m >> 10, t = m & 1023;
                const int h  = n >> 6,  dh = n & 63;
                const size_t idx = (((size_t)(nb * NH + h)) * TT + t) * DH + dh;
                if (MODE == 1) {
                    C0[idx] = val;
                } else {
                    C0[idx] = val + u[n];
                    C1[idx] = val + v[n];
                }
            }
        }
    }
}

// ---------------------------------------------------------------------------
// Fused score kernel with rel-shift folded in:
//   S[bh, i, j] = (Q_i+u)·K_j  +  (Q_i+v)·R[i - j + T - 1, head]
// 128x128 tile, 256 threads, 8x8 strided micro-tile. R held as a 255-row band;
// only 15 distinct diagonals are needed per thread per k.
// ---------------------------------------------------------------------------
__global__ __launch_bounds__(256) void score_kernel()
{
    __shared__ float Qus[16][129];
    __shared__ float Qvs[16][129];
    __shared__ float Ks [16][129];
    __shared__ float Rbs[16][258];   // 255 rows used

    const int bh = blockIdx.z;
    const int h  = bh & 15;
    const int i0 = blockIdx.y * 128;
    const int j0 = blockIdx.x * 128;
    const int tid = threadIdx.x;
    const int tx = tid & 15, ty = tid >> 4;

    const float* Qu = g_Qu + (size_t)bh * TT * DH;
    const float* Qv = g_Qv + (size_t)bh * TT * DH;
    const float* Kp = g_K  + (size_t)bh * TT * DH;

    // global R row = (i0+il) - (j0+jl) + 1023 ; local band index = il-jl+127
    const int rbase = i0 - j0 + 896;   // in [0, 1792]

    const int lrow = tid >> 2;
    const int lc4  = (tid & 3) * 4;

    float acc[8][8] = {};

    for (int k0 = 0; k0 < 64; k0 += 16) {
        #pragma unroll
        for (int q = 0; q < 2; q++) {
            const int row = lrow + q * 64;
            float4 a = *(const float4*)(Qu + (size_t)(i0 + row) * DH + k0 + lc4);
            Qus[lc4 + 0][row] = a.x; Qus[lc4 + 1][row] = a.y;
            Qus[lc4 + 2][row] = a.z; Qus[lc4 + 3][row] = a.w;
            float4 b = *(const float4*)(Qv + (size_t)(i0 + row) * DH + k0 + lc4);
            Qvs[lc4 + 0][row] = b.x; Qvs[lc4 + 1][row] = b.y;
            Qvs[lc4 + 2][row] = b.z; Qvs[lc4 + 3][row] = b.w;
            float4 c = *(const float4*)(Kp + (size_t)(j0 + row) * DH + k0 + lc4);
            Ks[lc4 + 0][row] = c.x; Ks[lc4 + 1][row] = c.y;
            Ks[lc4 + 2][row] = c.z; Ks[lc4 + 3][row] = c.w;
        }
        // R band: 255 rows x 16 cols -> 1020 float4 loads
        #pragma unroll
        for (int q = 0; q < 4; q++) {
            const int f = tid + q * 256;
            if (f < 1020) {
                const int row = f >> 2;
                const int c4 = (f & 3) * 4;
                float4 r = *(const float4*)(g_R + (size_t)(rbase + row) * DM + h * DH + k0 + c4);
                Rbs[c4 + 0][row] = r.x; Rbs[c4 + 1][row] = r.y;
                Rbs[c4 + 2][row] = r.z; Rbs[c4 + 3][row] = r.w;
            }
        }
        __syncthreads();

        #pragma unroll 4
        for (int kk = 0; kk < 16; kk++) {
            float ra[8], rv[8], rb[8], rr[15];
            #pragma unroll
            for (int ii = 0; ii < 8; ii++) {
                ra[ii] = Qus[kk][ty + 16 * ii];
                rv[ii] = Qvs[kk][ty + 16 * ii];
            }
            #pragma unroll
            for (int jj = 0; jj < 8; jj++) rb[jj] = Ks[kk][tx + 16 * jj];
            #pragma unroll
            for (int dd = 0; dd < 15; dd++) rr[dd] = Rbs[kk][ty - tx + 16 * dd + 15];
            #pragma unroll
            for (int ii = 0; ii < 8; ii++)
                #pragma unroll
                for (int jj = 0; jj < 8; jj++) {
                    float t = fmaf(ra[ii], rb[jj], acc[ii][jj]);
                    acc[ii][jj] = fmaf(rv[ii], rr[ii - jj + 7], t);
                }
        }
        __syncthreads();
    }

    float* Sp = g_S + (size_t)bh * TT * TT;
    #pragma unroll
    for (int ii = 0; ii < 8; ii++) {
        const int i = i0 + ty + 16 * ii;
        #pragma unroll
        for (int jj = 0; jj < 8; jj++) {
            Sp[(size_t)i * TT + j0 + tx + 16 * jj] = acc[ii][jj];
        }
    }
}

// ---------------------------------------------------------------------------
// Row softmax over S, scale = d^-0.5 = 0.125 applied to logits.
// ---------------------------------------------------------------------------
__global__ void softmax_kernel()
{
    const int row = blockIdx.x;
    float* p = g_S + (size_t)row * TT;
    const int tid = threadIdx.x;    // 256
    const float scale = 0.125f;

    float v[4];
    float m = -1e30f;
    #pragma unroll
    for (int q = 0; q < 4; q++) {
        v[q] = p[tid + q * 256] * scale;
        m = fmaxf(m, v[q]);
    }

    __shared__ float red[256];
    red[tid] = m;
    __syncthreads();
    for (int s = 128; s > 0; s >>= 1) {
        if (tid < s) red[tid] = fmaxf(red[tid], red[tid + s]);
        __syncthreads();
    }
    m = red[0];
    __syncthreads();

    float sum = 0.f;
    #pragma unroll
    for (int q = 0; q < 4; q++) {
        v[q] = expf(v[q] - m);
        sum += v[q];
    }
    red[tid] = sum;
    __syncthreads();
    for (int s = 128; s > 0; s >>= 1) {
        if (tid < s) red[tid] += red[tid + s];
        __syncthreads();
    }
    const float inv = 1.f / red[0];
    #pragma unroll
    for (int q = 0; q < 4; q++) {
        p[tid + q * 256] = v[q] * inv;
    }
}

// ---------------------------------------------------------------------------
// O = attn @ V per (n,h), written into (N, T, H*d) concat layout.
// 128(t) x 64(d) tile, 128 threads, 8x8 strided micro-tile.
// ---------------------------------------------------------------------------
__global__ __launch_bounds__(128) void av_kernel()
{
    __shared__ float As[16][129];   // [k][t]
    __shared__ float Vs[16][65];    // [k][n]

    const int bh = blockIdx.y;
    const int m0 = blockIdx.x * 128;
    const float* A  = g_S + (size_t)bh * TT * TT;
    const float* Vp = g_V + (size_t)bh * TT * DH;

    const int tid = threadIdx.x;       // 128
    const int tx = tid & 7, ty = tid >> 3;   // tx 0..7, ty 0..15

    float acc[8][8] = {};

    for (int k0 = 0; k0 < 1024; k0 += 16) {
        // A tile: 128 rows x 16 cols = 512 float4, 4 per thread
        #pragma unroll
        for (int q = 0; q < 4; q++) {
            const int row = (tid >> 2) + q * 32;
            const int c4 = (tid & 3) * 4;
            float4 av = *(const float4*)(A + (size_t)(m0 + row) * TT + k0 + c4);
            As[c4 + 0][row] = av.x; As[c4 + 1][row] = av.y;
            As[c4 + 2][row] = av.z; As[c4 + 3][row] = av.w;
        }
        // V tile: 16 rows x 64 cols = 256 float4, 2 per thread
        #pragma unroll
        for (int q = 0; q < 2; q++) {
            const int vrow = (tid >> 4) + q * 8;
            const int vc4 = (tid & 15) * 4;
            float4 vv = *(const float4*)(Vp + (size_t)(k0 + vrow) * DH + vc4);
            Vs[vrow][vc4 + 0] = vv.x; Vs[vrow][vc4 + 1] = vv.y;
            Vs[vrow][vc4 + 2] = vv.z; Vs[vrow][vc4 + 3] = vv.w;
        }
        __syncthreads();

        #pragma unroll 4
        for (int kk = 0; kk < 16; kk++) {
            float ra[8], rb[8];
            #pragma unroll
            for (int ii = 0; ii < 8; ii++) ra[ii] = As[kk][ty + 16 * ii];
            #pragma unroll
            for (int jj = 0; jj < 8; jj++) rb[jj] = Vs[kk][tx + 8 * jj];
            #pragma unroll
            for (int ii = 0; ii < 8; ii++)
                #pragma unroll
                for (int jj = 0; jj < 8; jj++)
                    acc[ii][jj] = fmaf(ra[ii], rb[jj], acc[ii][jj]);
        }
        __syncthreads();
    }

    const int nb = bh >> 4, h = bh & 15;
    #pragma unroll
    for (int ii = 0; ii < 8; ii++) {
        const int t = m0 + ty + 16 * ii;
        #pragma unroll
        for (int jj = 0; jj < 8; jj++) {
            const int n = tx + 8 * jj;
            g_O[((size_t)nb * TT + t) * DM + h * DH + n] = acc[ii][jj];
        }
    }
}

// ---------------------------------------------------------------------------
extern "C" void kernel_launch(void* const* d_in, const int* in_sizes, int n_in,
                              void* d_out, int out_size)
{
    (void)in_sizes; (void)n_in; (void)out_size;
    const float* x      = (const float*)d_in[0];
    const float* rel_pe = (const float*)d_in[1];
    const float* Wq     = (const float*)d_in[2];
    const float* bq     = (const float*)d_in[3];
    const float* Wk     = (const float*)d_in[4];
    const float* bk     = (const float*)d_in[5];
    const float* Wv     = (const float*)d_in[6];
    const float* bv     = (const float*)d_in[7];
    const float* Wo     = (const float*)d_in[8];
    const float* bo     = (const float*)d_in[9];
    const float* Wr     = (const float*)d_in[10];
    const float* u      = (const float*)d_in[11];
    const float* v      = (const float*)d_in[12];
    float* out = (float*)d_out;

    float *pQu, *pQv, *pK, *pV, *pR, *pO;
    cudaGetSymbolAddress((void**)&pQu, g_Qu);
    cudaGetSymbolAddress((void**)&pQv, g_Qv);
    cudaGetSymbolAddress((void**)&pK,  g_K);
    cudaGetSymbolAddress((void**)&pV,  g_V);
    cudaGetSymbolAddress((void**)&pR,  g_R);
    cudaGetSymbolAddress((void**)&pO,  g_O);

    // Projections (128x128 tiles)
    sgemm_bt<2><<<dim3(32, 8), 256>>>(x, Wq, bq, pQu, pQv, u, v, NB * TT);
    sgemm_bt<1><<<dim3(32, 8), 256>>>(x, Wk, bk, pK, nullptr, nullptr, nullptr, NB * TT);
    sgemm_bt<1><<<dim3(32, 8), 256>>>(x, Wv, bv, pV, nullptr, nullptr, nullptr, NB * TT);
    sgemm_bt<0><<<dim3(16, 8), 256>>>(rel_pe, Wr, nullptr, pR, nullptr, nullptr, nullptr, RLEN);

    // Fused AC + rel-shifted BD scores
    score_kernel<<<dim3(TT / 128, TT / 128, NB * NH), 256>>>();

    // Softmax
    softmax_kernel<<<NB * NH * TT, 256>>>();

    // attn @ V -> (N,T,D)
    av_kernel<<<dim3(TT / 128, NB * NH), 128>>>();

    // Output projection
    sgemm_bt<0><<<dim3(32, 8), 256>>>(pO, Wo, bo, out, nullptr, nullptr, nullptr, NB * TT);
}

// round 7
// speedup vs baseline: 2.8939x; 1.6725x over previous
#include <cuda_runtime.h>
#include <cuda_bf16.h>
#include <math.h>
#include <stdint.h>

#define NB      4
#define TT      1024
#define DM      1024
#define NH      16
#define DH      64
#define RLEN    2047   // 2*T - 1

typedef __nv_bfloat16 bf16;

// ---------------- fp32 scratch ----------------
__device__ float g_Qu[(size_t)NB*NH*TT*DH];     // Q + u   (N,H,T,d)  fp32 (score input)
__device__ float g_Qv[(size_t)NB*NH*TT*DH];     // Q + v
__device__ float g_K [(size_t)NB*NH*TT*DH];     // K
__device__ float g_R [(size_t)RLEN*DM];         // rel_pe @ Wr^T
__device__ float g_S [(size_t)NB*NH*TT*TT];     // scores (N,H,T,T)

// ---------------- bf16 split planes ----------------
__device__ bf16 g_xh [(size_t)NB*TT*DM],  g_xl [(size_t)NB*TT*DM];     // x
__device__ bf16 g_rph[(size_t)RLEN*DM],   g_rpl[(size_t)RLEN*DM];      // rel_pe
__device__ bf16 g_wqh[(size_t)DM*DM], g_wql[(size_t)DM*DM];
__device__ bf16 g_wkh[(size_t)DM*DM], g_wkl[(size_t)DM*DM];
__device__ bf16 g_wvh[(size_t)DM*DM], g_wvl[(size_t)DM*DM];
__device__ bf16 g_wrh[(size_t)DM*DM], g_wrl[(size_t)DM*DM];
__device__ bf16 g_woh[(size_t)DM*DM], g_wol[(size_t)DM*DM];
__device__ bf16 g_Vh [(size_t)NB*NH*DH*TT], g_Vl [(size_t)NB*NH*DH*TT];   // [bh][dh][t]
__device__ bf16 g_Ph [(size_t)NB*NH*TT*TT], g_Pl [(size_t)NB*NH*TT*TT];   // attn [bh*T + i][s]
__device__ bf16 g_Oh [(size_t)NB*TT*DM],   g_Ol [(size_t)NB*TT*DM];       // (N,T,D) concat

// ---------------------------------------------------------------------------
__device__ __forceinline__ uint32_t smem_u32(const void* p) {
    return (uint32_t)__cvta_generic_to_shared(p);
}
__device__ __forceinline__ void ldsm4(uint32_t* r, uint32_t addr) {
    asm volatile("ldmatrix.sync.aligned.m8n8.x4.shared.b16 {%0,%1,%2,%3}, [%4];"
                 : "=r"(r[0]), "=r"(r[1]), "=r"(r[2]), "=r"(r[3]) : "r"(addr));
}
__device__ __forceinline__ void mma16816(float* c, const uint32_t* a, const uint32_t* b) {
    asm volatile(
        "mma.sync.aligned.m16n8k16.row.col.f32.bf16.bf16.f32 "
        "{%0,%1,%2,%3}, {%4,%5,%6,%7}, {%8,%9}, {%0,%1,%2,%3};"
        : "+f"(c[0]), "+f"(c[1]), "+f"(c[2]), "+f"(c[3])
        : "r"(a[0]), "r"(a[1]), "r"(a[2]), "r"(a[3]), "r"(b[0]), "r"(b[1]));
}

// ---------------------------------------------------------------------------
// split fp32 -> bf16 hi/lo planes
// ---------------------------------------------------------------------------
__global__ void split_kernel(const float* __restrict__ s,
                             bf16* __restrict__ h, bf16* __restrict__ l, int n)
{
    int i = blockIdx.x * 256 + threadIdx.x;
    if (i < n) {
        float v = s[i];
        bf16 hv = __float2bfloat16(v);
        h[i] = hv;
        l[i] = __float2bfloat16(v - __bfloat162float(hv));
    }
}

// ---------------------------------------------------------------------------
// bf16x3-split tensor-core GEMM: C = A(MxK) @ B^T, K=1024, B stored [n][k].
// BM=128, BK=32, 256 threads (8 warps, 4x2), warp tile 32 x WN.
// MODE 0: Q proj  -> fp32 g_Qu/g_Qv head layout, + bias + u / + v
// MODE 1: K proj  -> fp32 head layout + bias
// MODE 2: V proj  -> bf16 hi/lo planes [bh][dh][t] + bias
// MODE 3: R proj  -> fp32 flat [m][n], no bias, M-guard
// MODE 4: out proj-> fp32 flat + bias
// MODE 5: attn@V  -> batched over bh (grid.z), bf16 hi/lo (N,T,D) concat
// ---------------------------------------------------------------------------
template<int MODE, int BN, int WN, bool MG>
__global__ __launch_bounds__(256) void mma_gemm(
    const bf16* __restrict__ Ah, const bf16* __restrict__ Al,
    const bf16* __restrict__ Bh, const bf16* __restrict__ Bl,
    const float* __restrict__ bias, const float* __restrict__ uu,
    const float* __restrict__ vv,
    float* __restrict__ o0, float* __restrict__ o1,
    bf16* __restrict__ oh, bf16* __restrict__ ol, int M)
{
    constexpr int NN = WN / 8;            // n-frags per warp
    __shared__ bf16 As[2][128][40];
    __shared__ bf16 Bs[2][BN][40];

    const int tid  = threadIdx.x;
    const int w    = tid >> 5, lane = tid & 31;
    const int wm   = w & 3,   wn   = w >> 2;
    const int m0   = blockIdx.x * 128, n0 = blockIdx.y * BN;

    const bf16* Aps[2] = {Ah, Al};
    const bf16* Bps[2] = {Bh, Bl};
    size_t abase = 0, bbase = 0;
    if (MODE == 5) { abase = (size_t)blockIdx.z << 20; bbase = (size_t)blockIdx.z << 16; }

    float acc[2][NN][4] = {};

    for (int k0 = 0; k0 < 1024; k0 += 32) {
        #pragma unroll
        for (int p = 0; p < 2; p++)
            #pragma unroll
            for (int it = 0; it < 2; it++) {
                int id = tid + it * 256;
                int r = id >> 2, c = id & 3;
                uint4 val = make_uint4(0u, 0u, 0u, 0u);
                if (!MG || (m0 + r) < M)
                    val = *(const uint4*)(Aps[p] + abase + (size_t)(m0 + r) * 1024 + k0 + c * 8);
                *(uint4*)&As[p][r][c * 8] = val;
            }
        #pragma unroll
        for (int p = 0; p < 2; p++)
            #pragma unroll
            for (int it = 0; it < BN / 64; it++) {
                int id = tid + it * 256;
                int r = id >> 2, c = id & 3;
                *(uint4*)&Bs[p][r][c * 8] =
                    *(const uint4*)(Bps[p] + bbase + (size_t)(n0 + r) * 1024 + k0 + c * 8);
            }
        __syncthreads();

        #pragma unroll
        for (int ks = 0; ks < 32; ks += 16) {
            uint32_t a[2][2][4];
            #pragma unroll
            for (int p = 0; p < 2; p++)
                #pragma unroll
                for (int mi = 0; mi < 2; mi++) {
                    uint32_t ad = smem_u32(
                        &As[p][wm * 32 + mi * 16 + (lane & 15)][ks + ((lane >> 4) << 3)]);
                    ldsm4(a[p][mi], ad);
                }
            uint32_t b[2][NN][2];
            #pragma unroll
            for (int p = 0; p < 2; p++)
                #pragma unroll
                for (int pr = 0; pr < NN / 2; pr++) {
                    uint32_t t4[4];
                    uint32_t bd = smem_u32(
                        &Bs[p][wn * WN + pr * 16 + (lane & 7) + ((lane >> 4) << 3)]
                              [ks + (((lane >> 3) & 1) << 3)]);
                    ldsm4(t4, bd);
                    b[p][2 * pr    ][0] = t4[0]; b[p][2 * pr    ][1] = t4[1];
                    b[p][2 * pr + 1][0] = t4[2]; b[p][2 * pr + 1][1] = t4[3];
                }
            #pragma unroll
            for (int mi = 0; mi < 2; mi++)
                #pragma unroll
                for (int ni = 0; ni < NN; ni++) {
                    mma16816(acc[mi][ni], a[0][mi], b[0][ni]);   // hi*hi
                    mma16816(acc[mi][ni], a[0][mi], b[1][ni]);   // hi*lo
                    mma16816(acc[mi][ni], a[1][mi], b[0][ni]);   // lo*hi
                }
        }
        __syncthreads();
    }

    // ---- epilogue ----
    #pragma unroll
    for (int mi = 0; mi < 2; mi++)
        #pragma unroll
        for (int ni = 0; ni < NN; ni++)
            #pragma unroll
            for (int r4 = 0; r4 < 4; r4++) {
                const int m = m0 + wm * 32 + mi * 16 + (lane >> 2) + ((r4 & 2) ? 8 : 0);
                const int n = n0 + wn * WN + ni * 8 + ((lane & 3) << 1) + (r4 & 1);
                float val = acc[mi][ni][r4];
                if (MODE == 3) {
                    if (m < M) o0[(size_t)m * 1024 + n] = val;
                } else if (MODE == 4) {
                    o0[(size_t)m * 1024 + n] = val + bias[n];
                } else if (MODE == 5) {
                    const int bh = blockIdx.z;
                    const int nb = bh >> 4, h = bh & 15;
                    const size_t idx = ((size_t)nb * 1024 + m) * 1024 + h * 64 + n;
                    bf16 hv = __float2bfloat16(val);
                    oh[idx] = hv;
                    ol[idx] = __float2bfloat16(val - __bfloat162float(hv));
                } else {
                    val += bias[n];
                    const int nb = m >> 10, t = m & 1023;
                    const int h  = n >> 6,  dh = n & 63;
                    if (MODE == 0) {
                        const size_t idx = (((size_t)(nb * NH + h)) * TT + t) * DH + dh;
                        o0[idx] = val + uu[n];
                        o1[idx] = val + vv[n];
                    } else if (MODE == 1) {
                        const size_t idx = (((size_t)(nb * NH + h)) * TT + t) * DH + dh;
                        o0[idx] = val;
                    } else {   // MODE 2: V -> [bh][dh][t] bf16 planes
                        const size_t idx = ((size_t)(nb * NH + h) * DH + dh) * TT + t;
                        bf16 hv = __float2bfloat16(val);
                        oh[idx] = hv;
                        ol[idx] = __float2bfloat16(val - __bfloat162float(hv));
                    }
                }
            }
}

// ---------------------------------------------------------------------------
// Fused score kernel (fp32):  S = (Q+u)K^T + rel-shifted (Q+v)R^T
// ---------------------------------------------------------------------------
__global__ __launch_bounds__(256) void score_kernel()
{
    __shared__ float Qus[16][129];
    __shared__ float Qvs[16][129];
    __shared__ float Ks [16][129];
    __shared__ float Rbs[16][258];

    const int bh = blockIdx.z;
    const int h  = bh & 15;
    const int i0 = blockIdx.y * 128;
    const int j0 = blockIdx.x * 128;
    const int tid = threadIdx.x;
    const int tx = tid & 15, ty = tid >> 4;

    const float* Qu = g_Qu + (size_t)bh * TT * DH;
    const float* Qv = g_Qv + (size_t)bh * TT * DH;
    const float* Kp = g_K  + (size_t)bh * TT * DH;

    const int rbase = i0 - j0 + 896;

    const int lrow = tid >> 2;
    const int lc4  = (tid & 3) * 4;

    float acc[8][8] = {};

    for (int k0 = 0; k0 < 64; k0 += 16) {
        #pragma unroll
        for (int q = 0; q < 2; q++) {
            const int row = lrow + q * 64;
            float4 a = *(const float4*)(Qu + (size_t)(i0 + row) * DH + k0 + lc4);
            Qus[lc4 + 0][row] = a.x; Qus[lc4 + 1][row] = a.y;
            Qus[lc4 + 2][row] = a.z; Qus[lc4 + 3][row] = a.w;
            float4 b = *(const float4*)(Qv + (size_t)(i0 + row) * DH + k0 + lc4);
            Qvs[lc4 + 0][row] = b.x; Qvs[lc4 + 1][row] = b.y;
            Qvs[lc4 + 2][row] = b.z; Qvs[lc4 + 3][row] = b.w;
            float4 c = *(const float4*)(Kp + (size_t)(j0 + row) * DH + k0 + lc4);
            Ks[lc4 + 0][row] = c.x; Ks[lc4 + 1][row] = c.y;
            Ks[lc4 + 2][row] = c.z; Ks[lc4 + 3][row] = c.w;
        }
        #pragma unroll
        for (int q = 0; q < 4; q++) {
            const int f = tid + q * 256;
            if (f < 1020) {
                const int row = f >> 2;
                const int c4 = (f & 3) * 4;
                float4 r = *(const float4*)(g_R + (size_t)(rbase + row) * DM + h * DH + k0 + c4);
                Rbs[c4 + 0][row] = r.x; Rbs[c4 + 1][row] = r.y;
                Rbs[c4 + 2][row] = r.z; Rbs[c4 + 3][row] = r.w;
            }
        }
        __syncthreads();

        #pragma unroll 4
        for (int kk = 0; kk < 16; kk++) {
            float ra[8], rv[8], rb[8], rr[15];
            #pragma unroll
            for (int ii = 0; ii < 8; ii++) {
                ra[ii] = Qus[kk][ty + 16 * ii];
                rv[ii] = Qvs[kk][ty + 16 * ii];
            }
            #pragma unroll
            for (int jj = 0; jj < 8; jj++) rb[jj] = Ks[kk][tx + 16 * jj];
            #pragma unroll
            for (int dd = 0; dd < 15; dd++) rr[dd] = Rbs[kk][ty - tx + 16 * dd + 15];
            #pragma unroll
            for (int ii = 0; ii < 8; ii++)
                #pragma unroll
                for (int jj = 0; jj < 8; jj++) {
                    float t = fmaf(ra[ii], rb[jj], acc[ii][jj]);
                    acc[ii][jj] = fmaf(rv[ii], rr[ii - jj + 7], t);
                }
        }
        __syncthreads();
    }

    float* Sp = g_S + (size_t)bh * TT * TT;
    #pragma unroll
    for (int ii = 0; ii < 8; ii++) {
        const int i = i0 + ty + 16 * ii;
        #pragma unroll
        for (int jj = 0; jj < 8; jj++) {
            Sp[(size_t)i * TT + j0 + tx + 16 * jj] = acc[ii][jj];
        }
    }
}

// ---------------------------------------------------------------------------
// Row softmax; writes attn as bf16 hi/lo planes for the tensor-core AV GEMM.
// ---------------------------------------------------------------------------
__global__ void softmax_kernel()
{
    const int row = blockIdx.x;
    const float* p = g_S + (size_t)row * TT;
    const int tid = threadIdx.x;    // 256
    const float scale = 0.125f;

    float v[4];
    float m = -1e30f;
    #pragma unroll
    for (int q = 0; q < 4; q++) {
        v[q] = p[tid + q * 256] * scale;
        m = fmaxf(m, v[q]);
    }

    __shared__ float red[256];
    red[tid] = m;
    __syncthreads();
    for (int s = 128; s > 0; s >>= 1) {
        if (tid < s) red[tid] = fmaxf(red[tid], red[tid + s]);
        __syncthreads();
    }
    m = red[0];
    __syncthreads();

    float sum = 0.f;
    #pragma unroll
    for (int q = 0; q < 4; q++) {
        v[q] = expf(v[q] - m);
        sum += v[q];
    }
    red[tid] = sum;
    __syncthreads();
    for (int s = 128; s > 0; s >>= 1) {
        if (tid < s) red[tid] += red[tid + s];
        __syncthreads();
    }
    const float inv = 1.f / red[0];
    __syncthreads();

    bf16* ph = g_Ph + (size_t)row * TT;
    bf16* pl = g_Pl + (size_t)row * TT;
    #pragma unroll
    for (int q = 0; q < 4; q++) {
        const float pv = v[q] * inv;
        const bf16 hv = __float2bfloat16(pv);
        ph[tid + q * 256] = hv;
        pl[tid + q * 256] = __float2bfloat16(pv - __bfloat162float(hv));
    }
}

// ---------------------------------------------------------------------------
extern "C" void kernel_launch(void* const* d_in, const int* in_sizes, int n_in,
                              void* d_out, int out_size)
{
    (void)in_sizes; (void)n_in; (void)out_size;
    const float* x      = (const float*)d_in[0];
    const float* rel_pe = (const float*)d_in[1];
    const float* Wq     = (const float*)d_in[2];
    const float* bq     = (const float*)d_in[3];
    const float* Wk     = (const float*)d_in[4];
    const float* bk     = (const float*)d_in[5];
    const float* Wv     = (const float*)d_in[6];
    const float* bv     = (const float*)d_in[7];
    const float* Wo     = (const float*)d_in[8];
    const float* bo     = (const float*)d_in[9];
    const float* Wr     = (const float*)d_in[10];
    const float* u      = (const float*)d_in[11];
    const float* v      = (const float*)d_in[12];
    float* out = (float*)d_out;

    float *pQu, *pQv, *pK, *pR;
    bf16 *pxh, *pxl, *prh, *prl;
    bf16 *pwqh, *pwql, *pwkh, *pwkl, *pwvh, *pwvl, *pwrh, *pwrl, *pwoh, *pwol;
    bf16 *pVh, *pVl, *pPh, *pPl, *pOh, *pOl;
    cudaGetSymbolAddress((void**)&pQu, g_Qu);
    cudaGetSymbolAddress((void**)&pQv, g_Qv);
    cudaGetSymbolAddress((void**)&pK,  g_K);
    cudaGetSymbolAddress((void**)&pR,  g_R);
    cudaGetSymbolAddress((void**)&pxh, g_xh);  cudaGetSymbolAddress((void**)&pxl, g_xl);
    cudaGetSymbolAddress((void**)&prh, g_rph); cudaGetSymbolAddress((void**)&prl, g_rpl);
    cudaGetSymbolAddress((void**)&pwqh, g_wqh); cudaGetSymbolAddress((void**)&pwql, g_wql);
    cudaGetSymbolAddress((void**)&pwkh, g_wkh); cudaGetSymbolAddress((void**)&pwkl, g_wkl);
    cudaGetSymbolAddress((void**)&pwvh, g_wvh); cudaGetSymbolAddress((void**)&pwvl, g_wvl);
    cudaGetSymbolAddress((void**)&pwrh, g_wrh); cudaGetSymbolAddress((void**)&pwrl, g_wrl);
    cudaGetSymbolAddress((void**)&pwoh, g_woh); cudaGetSymbolAddress((void**)&pwol, g_wol);
    cudaGetSymbolAddress((void**)&pVh, g_Vh);  cudaGetSymbolAddress((void**)&pVl, g_Vl);
    cudaGetSymbolAddress((void**)&pPh, g_Ph);  cudaGetSymbolAddress((void**)&pPl, g_Pl);
    cudaGetSymbolAddress((void**)&pOh, g_Oh);  cudaGetSymbolAddress((void**)&pOl, g_Ol);

    // ---- split fp32 -> bf16 hi/lo planes ----
    const int NX = NB * TT * DM;          // 4M
    const int NR = RLEN * DM;             // ~2.1M
    const int NW = DM * DM;               // 1M
    split_kernel<<<(NX + 255) / 256, 256>>>(x,      pxh,  pxl,  NX);
    split_kernel<<<(NR + 255) / 256, 256>>>(rel_pe, prh,  prl,  NR);
    split_kernel<<<(NW + 255) / 256, 256>>>(Wq,     pwqh, pwql, NW);
    split_kernel<<<(NW + 255) / 256, 256>>>(Wk,     pwkh, pwkl, NW);
    split_kernel<<<(NW + 255) / 256, 256>>>(Wv,     pwvh, pwvl, NW);
    split_kernel<<<(NW + 255) / 256, 256>>>(Wr,     pwrh, pwrl, NW);
    split_kernel<<<(NW + 255) / 256, 256>>>(Wo,     pwoh, pwol, NW);

    // ---- projections on tensor cores ----
    mma_gemm<0, 128, 64, false><<<dim3(32, 8), 256>>>(
        pxh, pxl, pwqh, pwql, bq, u, v, pQu, pQv, nullptr, nullptr, NB * TT);
    mma_gemm<1, 128, 64, false><<<dim3(32, 8), 256>>>(
        pxh, pxl, pwkh, pwkl, bk, nullptr, nullptr, pK, nullptr, nullptr, nullptr, NB * TT);
    mma_gemm<2, 128, 64, false><<<dim3(32, 8), 256>>>(
        pxh, pxl, pwvh, pwvl, bv, nullptr, nullptr, nullptr, nullptr, pVh, pVl, NB * TT);
    mma_gemm<3, 128, 64, true><<<dim3(16, 8), 256>>>(
        prh, prl, pwrh, pwrl, nullptr, nullptr, nullptr, pR, nullptr, nullptr, nullptr, RLEN);

    // ---- fused AC + rel-shifted BD scores (fp32) ----
    score_kernel<<<dim3(TT / 128, TT / 128, NB * NH), 256>>>();

    // ---- softmax (emits bf16 hi/lo attn) ----
    softmax_kernel<<<NB * NH * TT, 256>>>();

    // ---- attn @ V on tensor cores (batched over bh) ----
    mma_gemm<5, 64, 32, false><<<dim3(8, 1, NB * NH), 256>>>(
        pPh, pPl, pVh, pVl, nullptr, nullptr, nullptr, nullptr, nullptr, pOh, pOl, TT);

    // ---- output projection ----
    mma_gemm<4, 128, 64, false><<<dim3(32, 8), 256>>>(
        pOh, pOl, pwoh, pwol, bo, nullptr, nullptr, out, nullptr, nullptr, nullptr, NB * TT);
}

// round 9
// speedup vs baseline: 3.0113x; 1.0406x over previous
#include <cuda_runtime.h>
#include <cuda_bf16.h>
#include <math.h>
#include <stdint.h>

#define NB      4
#define TT      1024
#define DM      1024
#define NH      16
#define DH      64
#define RLEN    2047   // 2*T - 1

typedef __nv_bfloat16 bf16;

// ---------------- fp32 scratch ----------------
__device__ float g_S [(size_t)NB*NH*TT*TT];     // scores (N,H,T,T)

// ---------------- bf16 split planes ----------------
__device__ bf16 g_xh [(size_t)NB*TT*DM],  g_xl [(size_t)NB*TT*DM];     // x
__device__ bf16 g_rph[(size_t)RLEN*DM],   g_rpl[(size_t)RLEN*DM];      // rel_pe
__device__ bf16 g_wqh[(size_t)DM*DM], g_wql[(size_t)DM*DM];
__device__ bf16 g_wkh[(size_t)DM*DM], g_wkl[(size_t)DM*DM];
__device__ bf16 g_wvh[(size_t)DM*DM], g_wvl[(size_t)DM*DM];
__device__ bf16 g_wrh[(size_t)DM*DM], g_wrl[(size_t)DM*DM];
__device__ bf16 g_woh[(size_t)DM*DM], g_wol[(size_t)DM*DM];
__device__ bf16 g_Quh[(size_t)NB*NH*TT*DH], g_Qul[(size_t)NB*NH*TT*DH]; // Q+u [bh][t][dh]
__device__ bf16 g_Qvh[(size_t)NB*NH*TT*DH], g_Qvl[(size_t)NB*NH*TT*DH]; // Q+v
__device__ bf16 g_Kh [(size_t)NB*NH*TT*DH], g_Kl [(size_t)NB*NH*TT*DH]; // K   [bh][t][dh]
__device__ bf16 g_Rh [(size_t)RLEN*DM],     g_Rl [(size_t)RLEN*DM];     // R   [r][D]
__device__ bf16 g_Vh [(size_t)NB*NH*DH*TT], g_Vl [(size_t)NB*NH*DH*TT]; // V   [bh][dh][t]
__device__ bf16 g_Ph [(size_t)NB*NH*TT*TT], g_Pl [(size_t)NB*NH*TT*TT]; // attn
__device__ bf16 g_Oh [(size_t)NB*TT*DM],    g_Ol [(size_t)NB*TT*DM];    // (N,T,D) concat

// ---------------------------------------------------------------------------
__device__ __forceinline__ uint32_t smem_u32(const void* p) {
    return (uint32_t)__cvta_generic_to_shared(p);
}
__device__ __forceinline__ void ldsm4(uint32_t* r, uint32_t addr) {
    asm volatile("ldmatrix.sync.aligned.m8n8.x4.shared.b16 {%0,%1,%2,%3}, [%4];"
                 : "=r"(r[0]), "=r"(r[1]), "=r"(r[2]), "=r"(r[3]) : "r"(addr));
}
__device__ __forceinline__ void mma16816(float* c, const uint32_t* a, const uint32_t* b) {
    asm volatile(
        "mma.sync.aligned.m16n8k16.row.col.f32.bf16.bf16.f32 "
        "{%0,%1,%2,%3}, {%4,%5,%6,%7}, {%8,%9}, {%0,%1,%2,%3};"
        : "+f"(c[0]), "+f"(c[1]), "+f"(c[2]), "+f"(c[3])
        : "r"(a[0]), "r"(a[1]), "r"(a[2]), "r"(a[3]), "r"(b[0]), "r"(b[1]));
}
__device__ __forceinline__ void split_store(float v, bf16* __restrict__ h,
                                            bf16* __restrict__ l, size_t idx) {
    bf16 hv = __float2bfloat16(v);
    h[idx] = hv;
    l[idx] = __float2bfloat16(v - __bfloat162float(hv));
}

// ---------------------------------------------------------------------------
// split fp32 -> bf16 hi/lo planes
// ---------------------------------------------------------------------------
__global__ void split_kernel(const float* __restrict__ s,
                             bf16* __restrict__ h, bf16* __restrict__ l, int n)
{
    int i = blockIdx.x * 256 + threadIdx.x;
    if (i < n) split_store(s[i], h, l, i);
}

// ---------------------------------------------------------------------------
// bf16x3-split tensor-core GEMM: C = A(MxK) @ B^T, K=1024, B stored [n][k].
// BM=128, BK=32, 256 threads (8 warps, 4x2), warp tile 32 x WN.
// MODE 0: Q proj  -> bf16 planes: oh/ol = Q+bias+u, oh2/ol2 = Q+bias+v  [bh][t][dh]
// MODE 1: K proj  -> bf16 planes oh/ol [bh][t][dh]
// MODE 2: V proj  -> bf16 planes oh/ol [bh][dh][t]
// MODE 3: R proj  -> bf16 planes oh/ol [m][1024], no bias, M-guard
// MODE 4: out proj-> fp32 flat o0 + bias
// MODE 5: attn@V  -> batched over bh (grid.z), bf16 planes (N,T,D) concat
// ---------------------------------------------------------------------------
template<int MODE, int BN, int WN, bool MG>
__global__ __launch_bounds__(256) void mma_gemm(
    const bf16* __restrict__ Ah, const bf16* __restrict__ Al,
    const bf16* __restrict__ Bh, const bf16* __restrict__ Bl,
    const float* __restrict__ bias, const float* __restrict__ uu,
    const float* __restrict__ vv,
    float* __restrict__ o0,
    bf16* __restrict__ oh, bf16* __restrict__ ol,
    bf16* __restrict__ oh2, bf16* __restrict__ ol2, int M)
{
    constexpr int NN = WN / 8;            // n-frags per warp
    __shared__ bf16 As[2][128][40];
    __shared__ bf16 Bs[2][BN][40];

    const int tid  = threadIdx.x;
    const int w    = tid >> 5, lane = tid & 31;
    const int wm   = w & 3,   wn   = w >> 2;
    const int m0   = blockIdx.x * 128, n0 = blockIdx.y * BN;

    const bf16* Aps[2] = {Ah, Al};
    const bf16* Bps[2] = {Bh, Bl};
    size_t abase = 0, bbase = 0;
    if (MODE == 5) { abase = (size_t)blockIdx.z << 20; bbase = (size_t)blockIdx.z << 16; }

    float acc[2][NN][4] = {};

    for (int k0 = 0; k0 < 1024; k0 += 32) {
        #pragma unroll
        for (int p = 0; p < 2; p++)
            #pragma unroll
            for (int it = 0; it < 2; it++) {
                int id = tid + it * 256;
                int r = id >> 2, c = id & 3;
                uint4 val = make_uint4(0u, 0u, 0u, 0u);
                if (!MG || (m0 + r) < M)
                    val = *(const uint4*)(Aps[p] + abase + (size_t)(m0 + r) * 1024 + k0 + c * 8);
                *(uint4*)&As[p][r][c * 8] = val;
            }
        #pragma unroll
        for (int p = 0; p < 2; p++)
            #pragma unroll
            for (int it = 0; it < BN / 64; it++) {
                int id = tid + it * 256;
                int r = id >> 2, c = id & 3;
                *(uint4*)&Bs[p][r][c * 8] =
                    *(const uint4*)(Bps[p] + bbase + (size_t)(n0 + r) * 1024 + k0 + c * 8);
            }
        __syncthreads();

        #pragma unroll
        for (int ks = 0; ks < 32; ks += 16) {
            uint32_t a[2][2][4];
            #pragma unroll
            for (int p = 0; p < 2; p++)
                #pragma unroll
                for (int mi = 0; mi < 2; mi++) {
                    uint32_t ad = smem_u32(
                        &As[p][wm * 32 + mi * 16 + (lane & 15)][ks + ((lane >> 4) << 3)]);
                    ldsm4(a[p][mi], ad);
                }
            uint32_t b[2][NN][2];
            #pragma unroll
            for (int p = 0; p < 2; p++)
                #pragma unroll
                for (int pr = 0; pr < NN / 2; pr++) {
                    uint32_t t4[4];
                    uint32_t bd = smem_u32(
                        &Bs[p][wn * WN + pr * 16 + (lane & 7) + ((lane >> 4) << 3)]
                              [ks + (((lane >> 3) & 1) << 3)]);
                    ldsm4(t4, bd);
                    b[p][2 * pr    ][0] = t4[0]; b[p][2 * pr    ][1] = t4[1];
                    b[p][2 * pr + 1][0] = t4[2]; b[p][2 * pr + 1][1] = t4[3];
                }
            #pragma unroll
            for (int mi = 0; mi < 2; mi++)
                #pragma unroll
                for (int ni = 0; ni < NN; ni++) {
                    mma16816(acc[mi][ni], a[0][mi], b[0][ni]);   // hi*hi
                    mma16816(acc[mi][ni], a[0][mi], b[1][ni]);   // hi*lo
                    mma16816(acc[mi][ni], a[1][mi], b[0][ni]);   // lo*hi
                }
        }
        __syncthreads();
    }

    // ---- epilogue ----
    #pragma unroll
    for (int mi = 0; mi < 2; mi++)
        #pragma unroll
        for (int ni = 0; ni < NN; ni++)
            #pragma unroll
            for (int r4 = 0; r4 < 4; r4++) {
                const int m = m0 + wm * 32 + mi * 16 + (lane >> 2) + ((r4 & 2) ? 8 : 0);
                const int n = n0 + wn * WN + ni * 8 + ((lane & 3) << 1) + (r4 & 1);
                float val = acc[mi][ni][r4];
                if (MODE == 3) {
                    if (m < M) split_store(val, oh, ol, (size_t)m * 1024 + n);
                } else if (MODE == 4) {
                    o0[(size_t)m * 1024 + n] = val + bias[n];
                } else if (MODE == 5) {
                    const int bh = blockIdx.z;
                    const int nb = bh >> 4, h = bh & 15;
                    split_store(val, oh, ol, ((size_t)nb * 1024 + m) * 1024 + h * 64 + n);
                } else {
                    val += bias[n];
                    const int nb = m >> 10, t = m & 1023;
                    const int h  = n >> 6,  dh = n & 63;
                    if (MODE == 0) {
                        const size_t idx = (((size_t)(nb * NH + h)) * TT + t) * DH + dh;
                        split_store(val + uu[n], oh,  ol,  idx);
                        split_store(val + vv[n], oh2, ol2, idx);
                    } else if (MODE == 1) {
                        const size_t idx = (((size_t)(nb * NH + h)) * TT + t) * DH + dh;
                        split_store(val, oh, ol, idx);
                    } else {   // MODE 2: V -> [bh][dh][t]
                        const size_t idx = ((size_t)(nb * NH + h) * DH + dh) * TT + t;
                        split_store(val, oh, ol, idx);
                    }
                }
            }
}

// ---------------------------------------------------------------------------
// Tensor-core score kernel with rel-shift fused via fragment scatter.
//   Tile: 64 (i) x 128 (j).  Band: 192 R rows.
//   Phase 1: BD = Qv(64x64) @ Rband^T(192x64); scatter (il,rl)->(il,jl=il-rl+127)
//            into fp32 smem Ss (bijective over the tile -> plain stores).
//   Phase 2: AC = Qu(64x64) @ K^T(128x64); S = AC + Ss -> g_S fp32.
// Dynamic smem: Ss 64x132 f32 (33792 B) | A 2x64x72 bf16 (18432 B)
//               | B 2x192x72 bf16 (55296 B)  = 107520 B; 2 CTAs/SM.
// ---------------------------------------------------------------------------
#define SMEM_SCORE 107520
__global__ __launch_bounds__(256, 2) void score_mma_kernel()
{
    extern __shared__ char smem[];
    float* Ss = (float*)smem;                       // [64][132]
    bf16* A0 = (bf16*)(smem + 33792);               // plane stride 4608 (64x72)
    bf16* B0 = (bf16*)(smem + 52224);               // p1 stride 13824 (192x72); p2 9216 (128x72)

    const int tid = threadIdx.x;
    const int w = tid >> 5, lane = tid & 31;
    const int wm = w & 1, wn = w >> 1;              // 2 x 4 warps
    const int j0 = blockIdx.x * 128;
    const int i0 = blockIdx.y * 64;
    const int bh = blockIdx.z;
    const int h  = bh & 15;
    const int rb0 = i0 - j0 + 896;                  // in [0, 1856]

    // ===== phase 1: load Qv + R band =====
    {
        const bf16* Qvp[2] = {g_Qvh, g_Qvl};
        #pragma unroll
        for (int p = 0; p < 2; p++)
            #pragma unroll
            for (int it = 0; it < 2; it++) {
                int id = tid + it * 256;            // 0..511
                int r = id >> 3, c8 = id & 7;
                *(uint4*)(A0 + p * 4608 + r * 72 + c8 * 8) =
                    *(const uint4*)(Qvp[p] + ((size_t)bh * 1024 + i0 + r) * 64 + c8 * 8);
            }
        const bf16* Rp[2] = {g_Rh, g_Rl};
        #pragma unroll
        for (int p = 0; p < 2; p++)
            #pragma unroll
            for (int it = 0; it < 6; it++) {
                int id = tid + it * 256;            // 0..1535
                int r = id >> 3, c8 = id & 7;
                int grow = rb0 + r; if (grow > 2046) grow = 2046;   // row 191 unused
                *(uint4*)(B0 + p * 13824 + r * 72 + c8 * 8) =
                    *(const uint4*)(Rp[p] + (size_t)grow * 1024 + h * 64 + c8 * 8);
            }
    }
    __syncthreads();

    // ===== phase 1: BD MMA (64 x 192) + scatter =====
    {
        float acc[2][6][4] = {};
        #pragma unroll
        for (int ks = 0; ks < 64; ks += 16) {
            uint32_t a[2][2][4];
            #pragma unroll
            for (int p = 0; p < 2; p++)
                #pragma unroll
                for (int mi = 0; mi < 2; mi++)
                    ldsm4(a[p][mi], smem_u32(A0 + p * 4608 +
                        (wm * 32 + mi * 16 + (lane & 15)) * 72 + ks + ((lane >> 4) << 3)));
            uint32_t b[2][6][2];
            #pragma unroll
            for (int p = 0; p < 2; p++)
                #pragma unroll
                for (int pr = 0; pr < 3; pr++) {
                    uint32_t t4[4];
                    ldsm4(t4, smem_u32(B0 + p * 13824 +
                        (wn * 48 + pr * 16 + (lane & 7) + ((lane >> 4) << 3)) * 72 +
                        ks + (((lane >> 3) & 1) << 3)));
                    b[p][2 * pr    ][0] = t4[0]; b[p][2 * pr    ][1] = t4[1];
                    b[p][2 * pr + 1][0] = t4[2]; b[p][2 * pr + 1][1] = t4[3];
                }
            #pragma unroll
            for (int mi = 0; mi < 2; mi++)
                #pragma unroll
                for (int ni = 0; ni < 6; ni++) {
                    mma16816(acc[mi][ni], a[0][mi], b[0][ni]);
                    mma16816(acc[mi][ni], a[0][mi], b[1][ni]);
                    mma16816(acc[mi][ni], a[1][mi], b[0][ni]);
                }
        }
        // scatter band -> Ss (bijective: each (il,jl) written exactly once)
        #pragma unroll
        for (int mi = 0; mi < 2; mi++)
            #pragma unroll
            for (int ni = 0; ni < 6; ni++)
                #pragma unroll
                for (int r4 = 0; r4 < 4; r4++) {
                    const int il = wm * 32 + mi * 16 + (lane >> 2) + ((r4 & 2) ? 8 : 0);
                    const int rl = wn * 48 + ni * 8 + ((lane & 3) << 1) + (r4 & 1);
                    const int jl = il - rl + 127;
                    if (jl >= 0 && jl < 128) Ss[il * 132 + jl] = acc[mi][ni][r4];
                }
    }
    __syncthreads();

    // ===== phase 2: load Qu + K =====
    {
        const bf16* Qup[2] = {g_Quh, g_Qul};
        #pragma unroll
        for (int p = 0; p < 2; p++)
            #pragma unroll
            for (int it = 0; it < 2; it++) {
                int id = tid + it * 256;
                int r = id >> 3, c8 = id & 7;
                *(uint4*)(A0 + p * 4608 + r * 72 + c8 * 8) =
                    *(const uint4*)(Qup[p] + ((size_t)bh * 1024 + i0 + r) * 64 + c8 * 8);
            }
        const bf16* Kp[2] = {g_Kh, g_Kl};
        #pragma unroll
        for (int p = 0; p < 2; p++)
            #pragma unroll
            for (int it = 0; it < 4; it++) {
                int id = tid + it * 256;            // 0..1023
                int r = id >> 3, c8 = id & 7;
                *(uint4*)(B0 + p * 9216 + r * 72 + c8 * 8) =
                    *(const uint4*)(Kp[p] + ((size_t)bh * 1024 + j0 + r) * 64 + c8 * 8);
            }
    }
    __syncthreads();

    // ===== phase 2: AC MMA (64 x 128) + combine + store =====
    {
        float acc[2][4][4] = {};
        #pragma unroll
        for (int ks = 0; ks < 64; ks += 16) {
            uint32_t a[2][2][4];
            #pragma unroll
            for (int p = 0; p < 2; p++)
                #pragma unroll
                for (int mi = 0; mi < 2; mi++)
                    ldsm4(a[p][mi], smem_u32(A0 + p * 4608 +
                        (wm * 32 + mi * 16 + (lane & 15)) * 72 + ks + ((lane >> 4) << 3)));
            uint32_t b[2][4][2];
            #pragma unroll
            for (int p = 0; p < 2; p++)
                #pragma unroll
                for (int pr = 0; pr < 2; pr++) {
                    uint32_t t4[4];
                    ldsm4(t4, smem_u32(B0 + p * 9216 +
                        (wn * 32 + pr * 16 + (lane & 7) + ((lane >> 4) << 3)) * 72 +
                        ks + (((lane >> 3) & 1) << 3)));
                    b[p][2 * pr    ][0] = t4[0]; b[p][2 * pr    ][1] = t4[1];
                    b[p][2 * pr + 1][0] = t4[2]; b[p][2 * pr + 1][1] = t4[3];
                }
            #pragma unroll
            for (int mi = 0; mi < 2; mi++)
                #pragma unroll
                for (int ni = 0; ni < 4; ni++) {
                    mma16816(acc[mi][ni], a[0][mi], b[0][ni]);
                    mma16816(acc[mi][ni], a[0][mi], b[1][ni]);
                    mma16816(acc[mi][ni], a[1][mi], b[0][ni]);
                }
        }
        float* Sp = g_S + ((size_t)bh << 20);
        #pragma unroll
        for (int mi = 0; mi < 2; mi++)
            #pragma unroll
            for (int ni = 0; ni < 4; ni++)
                #pragma unroll
                for (int r4 = 0; r4 < 4; r4++) {
                    const int il = wm * 32 + mi * 16 + (lane >> 2) + ((r4 & 2) ? 8 : 0);
                    const int jl = wn * 32 + ni * 8 + ((lane & 3) << 1) + (r4 & 1);
                    Sp[(size_t)(i0 + il) * 1024 + j0 + jl] =
                        acc[mi][ni][r4] + Ss[il * 132 + jl];
                }
    }
}

// ---------------------------------------------------------------------------
// Row softmax; writes attn as bf16 hi/lo planes for the tensor-core AV GEMM.
// ---------------------------------------------------------------------------
__global__ void softmax_kernel()
{
    const int row = blockIdx.x;
    const float* p = g_S + (size_t)row * TT;
    const int tid = threadIdx.x;    // 256
    const float scale = 0.125f;

    float v[4];
    float m = -1e30f;
    #pragma unroll
    for (int q = 0; q < 4; q++) {
        v[q] = p[tid + q * 256] * scale;
        m = fmaxf(m, v[q]);
    }

    __shared__ float red[256];
    red[tid] = m;
    __syncthreads();
    for (int s = 128; s > 0; s >>= 1) {
        if (tid < s) red[tid] = fmaxf(red[tid], red[tid + s]);
        __syncthreads();
    }
    m = red[0];
    __syncthreads();

    float sum = 0.f;
    #pragma unroll
    for (int q = 0; q < 4; q++) {
        v[q] = expf(v[q] - m);
        sum += v[q];
    }
    red[tid] = sum;
    __syncthreads();
    for (int s = 128; s > 0; s >>= 1) {
        if (tid < s) red[tid] += red[tid + s];
        __syncthreads();
    }
    const float inv = 1.f / red[0];
    __syncthreads();

    bf16* ph = g_Ph + (size_t)row * TT;
    bf16* pl = g_Pl + (size_t)row * TT;
    #pragma unroll
    for (int q = 0; q < 4; q++) {
        const float pv = v[q] * inv;
        const bf16 hv = __float2bfloat16(pv);
        ph[tid + q * 256] = hv;
        pl[tid + q * 256] = __float2bfloat16(pv - __bfloat162float(hv));
    }
}

// ---------------------------------------------------------------------------
extern "C" void kernel_launch(void* const* d_in, const int* in_sizes, int n_in,
                              void* d_out, int out_size)
{
    (void)in_sizes; (void)n_in; (void)out_size;
    const float* x      = (const float*)d_in[0];
    const float* rel_pe = (const float*)d_in[1];
    const float* Wq     = (const float*)d_in[2];
    const float* bq     = (const float*)d_in[3];
    const float* Wk     = (const float*)d_in[4];
    const float* bk     = (const float*)d_in[5];
    const float* Wv     = (const float*)d_in[6];
    const float* bv     = (const float*)d_in[7];
    const float* Wo     = (const float*)d_in[8];
    const float* bo     = (const float*)d_in[9];
    const float* Wr     = (const float*)d_in[10];
    const float* u      = (const float*)d_in[11];
    const float* v      = (const float*)d_in[12];
    float* out = (float*)d_out;

    bf16 *pxh, *pxl, *prh, *prl;
    bf16 *pwqh, *pwql, *pwkh, *pwkl, *pwvh, *pwvl, *pwrh, *pwrl, *pwoh, *pwol;
    bf16 *pQuh, *pQul, *pQvh, *pQvl, *pKh, *pKl, *pRh, *pRl;
    bf16 *pVh, *pVl, *pPh, *pPl, *pOh, *pOl;
    cudaGetSymbolAddress((void**)&pxh, g_xh);  cudaGetSymbolAddress((void**)&pxl, g_xl);
    cudaGetSymbolAddress((void**)&prh, g_rph); cudaGetSymbolAddress((void**)&prl, g_rpl);
    cudaGetSymbolAddress((void**)&pwqh, g_wqh); cudaGetSymbolAddress((void**)&pwql, g_wql);
    cudaGetSymbolAddress((void**)&pwkh, g_wkh); cudaGetSymbolAddress((void**)&pwkl, g_wkl);
    cudaGetSymbolAddress((void**)&pwvh, g_wvh); cudaGetSymbolAddress((void**)&pwvl, g_wvl);
    cudaGetSymbolAddress((void**)&pwrh, g_wrh); cudaGetSymbolAddress((void**)&pwrl, g_wrl);
    cudaGetSymbolAddress((void**)&pwoh, g_woh); cudaGetSymbolAddress((void**)&pwol, g_wol);
    cudaGetSymbolAddress((void**)&pQuh, g_Quh); cudaGetSymbolAddress((void**)&pQul, g_Qul);
    cudaGetSymbolAddress((void**)&pQvh, g_Qvh); cudaGetSymbolAddress((void**)&pQvl, g_Qvl);
    cudaGetSymbolAddress((void**)&pKh, g_Kh);  cudaGetSymbolAddress((void**)&pKl, g_Kl);
    cudaGetSymbolAddress((void**)&pRh, g_Rh);  cudaGetSymbolAddress((void**)&pRl, g_Rl);
    cudaGetSymbolAddress((void**)&pVh, g_Vh);  cudaGetSymbolAddress((void**)&pVl, g_Vl);
    cudaGetSymbolAddress((void**)&pPh, g_Ph);  cudaGetSymbolAddress((void**)&pPl, g_Pl);
    cudaGetSymbolAddress((void**)&pOh, g_Oh);  cudaGetSymbolAddress((void**)&pOl, g_Ol);

    cudaFuncSetAttribute(score_mma_kernel,
                         cudaFuncAttributeMaxDynamicSharedMemorySize, SMEM_SCORE);

    // ---- split fp32 -> bf16 hi/lo planes ----
    const int NX = NB * TT * DM;          // 4M
    const int NR = RLEN * DM;             // ~2.1M
    const int NW = DM * DM;               // 1M
    split_kernel<<<(NX + 255) / 256, 256>>>(x,      pxh,  pxl,  NX);
    split_kernel<<<(NR + 255) / 256, 256>>>(rel_pe, prh,  prl,  NR);
    split_kernel<<<(NW + 255) / 256, 256>>>(Wq,     pwqh, pwql, NW);
    split_kernel<<<(NW + 255) / 256, 256>>>(Wk,     pwkh, pwkl, NW);
    split_kernel<<<(NW + 255) / 256, 256>>>(Wv,     pwvh, pwvl, NW);
    split_kernel<<<(NW + 255) / 256, 256>>>(Wr,     pwrh, pwrl, NW);
    split_kernel<<<(NW + 255) / 256, 256>>>(Wo,     pwoh, pwol, NW);

    // ---- projections on tensor cores (emit bf16 split planes) ----
    mma_gemm<0, 128, 64, false><<<dim3(32, 8), 256>>>(
        pxh, pxl, pwqh, pwql, bq, u, v, nullptr, pQuh, pQul, pQvh, pQvl, NB * TT);
    mma_gemm<1, 128, 64, false><<<dim3(32, 8), 256>>>(
        pxh, pxl, pwkh, pwkl, bk, nullptr, nullptr, nullptr, pKh, pKl, nullptr, nullptr, NB * TT);
    mma_gemm<2, 128, 64, false><<<dim3(32, 8), 256>>>(
        pxh, pxl, pwvh, pwvl, bv, nullptr, nullptr, nullptr, pVh, pVl, nullptr, nullptr, NB * TT);
    mma_gemm<3, 128, 64, true><<<dim3(16, 8), 256>>>(
        prh, prl, pwrh, pwrl, nullptr, nullptr, nullptr, nullptr, pRh, pRl, nullptr, nullptr, RLEN);

    // ---- fused AC + rel-shifted BD scores on tensor cores ----
    score_mma_kernel<<<dim3(TT / 128, TT / 64, NB * NH), 256, SMEM_SCORE>>>();

    // ---- softmax (emits bf16 hi/lo attn) ----
    softmax_kernel<<<NB * NH * TT, 256>>>();

    // ---- attn @ V on tensor cores (batched over bh) ----
    mma_gemm<5, 64, 32, false><<<dim3(8, 1, NB * NH), 256>>>(
        pPh, pPl, pVh, pVl, nullptr, nullptr, nullptr, nullptr, pOh, pOl, nullptr, nullptr, TT);

    // ---- output projection ----
    mma_gemm<4, 128, 64, false><<<dim3(32, 8), 256>>>(
        pOh, pOl, pwoh, pwol, bo, nullptr, nullptr, out, nullptr, nullptr, nullptr, nullptr, NB * TT);
}

// round 10
// speedup vs baseline: 3.5439x; 1.1768x over previous
#include <cuda_runtime.h>
#include <cuda_bf16.h>
#include <math.h>
#include <stdint.h>

#define NB      4
#define TT      1024
#define DM      1024
#define NH      16
#define DH      64
#define RLEN    2047   // 2*T - 1

typedef __nv_bfloat16 bf16;

// ---------------- fp32 scratch ----------------
__device__ float g_S [(size_t)NB*NH*TT*TT];     // scores (N,H,T,T)

// ---------------- bf16 split planes ----------------
__device__ bf16 g_xh [(size_t)NB*TT*DM],  g_xl [(size_t)NB*TT*DM];     // x
__device__ bf16 g_rph[(size_t)RLEN*DM],   g_rpl[(size_t)RLEN*DM];      // rel_pe
__device__ bf16 g_wqh[(size_t)DM*DM], g_wql[(size_t)DM*DM];
__device__ bf16 g_wkh[(size_t)DM*DM], g_wkl[(size_t)DM*DM];
__device__ bf16 g_wvh[(size_t)DM*DM], g_wvl[(size_t)DM*DM];
__device__ bf16 g_wrh[(size_t)DM*DM], g_wrl[(size_t)DM*DM];
__device__ bf16 g_woh[(size_t)DM*DM], g_wol[(size_t)DM*DM];
__device__ bf16 g_Quh[(size_t)NB*NH*TT*DH], g_Qul[(size_t)NB*NH*TT*DH]; // Q+u [bh][t][dh]
__device__ bf16 g_Qvh[(size_t)NB*NH*TT*DH], g_Qvl[(size_t)NB*NH*TT*DH]; // Q+v
__device__ bf16 g_Kh [(size_t)NB*NH*TT*DH], g_Kl [(size_t)NB*NH*TT*DH]; // K   [bh][t][dh]
__device__ bf16 g_Rh [(size_t)RLEN*DM],     g_Rl [(size_t)RLEN*DM];     // R   [r][D]
__device__ bf16 g_Vh [(size_t)NB*NH*DH*TT], g_Vl [(size_t)NB*NH*DH*TT]; // V   [bh][dh][t]
__device__ bf16 g_Ph [(size_t)NB*NH*TT*TT], g_Pl [(size_t)NB*NH*TT*TT]; // attn
__device__ bf16 g_Oh [(size_t)NB*TT*DM],    g_Ol [(size_t)NB*TT*DM];    // (N,T,D) concat

// ---------------------------------------------------------------------------
__device__ __forceinline__ uint32_t smem_u32(const void* p) {
    return (uint32_t)__cvta_generic_to_shared(p);
}
__device__ __forceinline__ void ldsm4(uint32_t* r, uint32_t addr) {
    asm volatile("ldmatrix.sync.aligned.m8n8.x4.shared.b16 {%0,%1,%2,%3}, [%4];"
                 : "=r"(r[0]), "=r"(r[1]), "=r"(r[2]), "=r"(r[3]) : "r"(addr));
}
__device__ __forceinline__ void mma16816(float* c, const uint32_t* a, const uint32_t* b) {
    asm volatile(
        "mma.sync.aligned.m16n8k16.row.col.f32.bf16.bf16.f32 "
        "{%0,%1,%2,%3}, {%4,%5,%6,%7}, {%8,%9}, {%0,%1,%2,%3};"
        : "+f"(c[0]), "+f"(c[1]), "+f"(c[2]), "+f"(c[3])
        : "r"(a[0]), "r"(a[1]), "r"(a[2]), "r"(a[3]), "r"(b[0]), "r"(b[1]));
}
__device__ __forceinline__ void split_store(float v, bf16* __restrict__ h,
                                            bf16* __restrict__ l, size_t idx) {
    bf16 hv = __float2bfloat16(v);
    h[idx] = hv;
    l[idx] = __float2bfloat16(v - __bfloat162float(hv));
}
__device__ __forceinline__ void cp16(const void* smem_ptr, const void* gptr, bool valid) {
    uint32_t sa = smem_u32(smem_ptr);
    int sz = valid ? 16 : 0;
    asm volatile("cp.async.cg.shared.global [%0], [%1], 16, %2;"
                 :: "r"(sa), "l"(gptr), "r"(sz) : "memory");
}

// ---------------------------------------------------------------------------
// split fp32 -> bf16 hi/lo planes
// ---------------------------------------------------------------------------
__global__ void split_kernel(const float* __restrict__ s,
                             bf16* __restrict__ h, bf16* __restrict__ l, int n)
{
    int i = blockIdx.x * 256 + threadIdx.x;
    if (i < n) split_store(s[i], h, l, i);
}

// ---------------------------------------------------------------------------
// bf16x3-split tensor-core GEMM with cp.async 2-stage pipeline.
// C = A(MxK) @ B^T, K=1024, B stored [n][k]. BM=128, BK=32, 256 threads.
// Dynamic smem: A stages 2 x 2planes x 128 x 40, B stages 2 x 2planes x BN x 40.
// MODE 0: Q proj -> planes Qu (oh/ol), Qv (oh2/ol2);  MODE 1: K proj planes;
// MODE 2: V proj planes [bh][dh][t];  MODE 3: R proj planes (M-guard);
// MODE 4: out proj fp32+bias;  MODE 5: attn@V batched (grid.z = bh).
// ---------------------------------------------------------------------------
template<int MODE, int BN, int WN, bool MG>
__global__ __launch_bounds__(256) void mma_gemm(
    const bf16* __restrict__ Ah, const bf16* __restrict__ Al,
    const bf16* __restrict__ Bh, const bf16* __restrict__ Bl,
    const float* __restrict__ bias, const float* __restrict__ uu,
    const float* __restrict__ vv,
    float* __restrict__ o0,
    bf16* __restrict__ oh, bf16* __restrict__ ol,
    bf16* __restrict__ oh2, bf16* __restrict__ ol2, int M)
{
    constexpr int NN = WN / 8;
    extern __shared__ bf16 sm[];
    bf16* Asm = sm;                    // [(s*2+p)*128 + r]*40 + c
    bf16* Bsm = sm + 2 * 2 * 128 * 40; // [(s*2+p)*BN + r]*40 + c

    const int tid  = threadIdx.x;
    const int w    = tid >> 5, lane = tid & 31;
    const int wm   = w & 3,   wn   = w >> 2;
    const int m0   = blockIdx.x * 128, n0 = blockIdx.y * BN;

    const bf16* Aps[2] = {Ah, Al};
    const bf16* Bps[2] = {Bh, Bl};
    size_t abase = 0, bbase = 0;
    if (MODE == 5) { abase = (size_t)blockIdx.z << 20; bbase = (size_t)blockIdx.z << 16; }

    auto load_stage = [&](int s, int kk0) {
        #pragma unroll
        for (int it = 0; it < 4; it++) {            // A: 2p x 128r x 4 chunks
            int id = tid + it * 256;
            int p = id >> 9, rem = id & 511;
            int r = rem >> 2, c = rem & 3;
            bool ok = !MG || (m0 + r) < M;
            cp16(Asm + ((size_t)(s * 2 + p) * 128 + r) * 40 + c * 8,
                 Aps[p] + abase + (size_t)(m0 + r) * 1024 + kk0 + c * 8, ok);
        }
        #pragma unroll
        for (int it = 0; it < BN / 32; it++) {      // B: 2p x BNr x 4 chunks
            int id = tid + it * 256;
            int p = id / (4 * BN), rem = id % (4 * BN);
            int r = rem >> 2, c = rem & 3;
            cp16(Bsm + ((size_t)(s * 2 + p) * BN + r) * 40 + c * 8,
                 Bps[p] + bbase + (size_t)(n0 + r) * 1024 + kk0 + c * 8, true);
        }
        asm volatile("cp.async.commit_group;" ::: "memory");
    };

    float acc[2][NN][4] = {};

    load_stage(0, 0);
    for (int k0 = 0; k0 < 32; k0++) {
        if (k0 + 1 < 32) {
            load_stage((k0 + 1) & 1, (k0 + 1) * 32);
            asm volatile("cp.async.wait_group 1;" ::: "memory");
        } else {
            asm volatile("cp.async.wait_group 0;" ::: "memory");
        }
        __syncthreads();

        const int s = k0 & 1;
        const bf16* Ab = Asm + (size_t)(s * 2) * 128 * 40;
        const bf16* Bb = Bsm + (size_t)(s * 2) * BN * 40;

        #pragma unroll
        for (int ks = 0; ks < 32; ks += 16) {
            uint32_t a[2][2][4];
            #pragma unroll
            for (int p = 0; p < 2; p++)
                #pragma unroll
                for (int mi = 0; mi < 2; mi++)
                    ldsm4(a[p][mi], smem_u32(Ab + (size_t)p * 128 * 40 +
                        (wm * 32 + mi * 16 + (lane & 15)) * 40 + ks + ((lane >> 4) << 3)));
            uint32_t b[2][NN][2];
            #pragma unroll
            for (int p = 0; p < 2; p++)
                #pragma unroll
                for (int pr = 0; pr < NN / 2; pr++) {
                    uint32_t t4[4];
                    ldsm4(t4, smem_u32(Bb + (size_t)p * BN * 40 +
                        (wn * WN + pr * 16 + (lane & 7) + ((lane >> 4) << 3)) * 40 +
                        ks + (((lane >> 3) & 1) << 3)));
                    b[p][2 * pr    ][0] = t4[0]; b[p][2 * pr    ][1] = t4[1];
                    b[p][2 * pr + 1][0] = t4[2]; b[p][2 * pr + 1][1] = t4[3];
                }
            #pragma unroll
            for (int mi = 0; mi < 2; mi++)
                #pragma unroll
                for (int ni = 0; ni < NN; ni++) {
                    mma16816(acc[mi][ni], a[0][mi], b[0][ni]);   // hi*hi
                    mma16816(acc[mi][ni], a[0][mi], b[1][ni]);   // hi*lo
                    mma16816(acc[mi][ni], a[1][mi], b[0][ni]);   // lo*hi
                }
        }
        __syncthreads();
    }

    // ---- epilogue ----
    #pragma unroll
    for (int mi = 0; mi < 2; mi++)
        #pragma unroll
        for (int ni = 0; ni < NN; ni++)
            #pragma unroll
            for (int r4 = 0; r4 < 4; r4++) {
                const int m = m0 + wm * 32 + mi * 16 + (lane >> 2) + ((r4 & 2) ? 8 : 0);
                const int n = n0 + wn * WN + ni * 8 + ((lane & 3) << 1) + (r4 & 1);
                float val = acc[mi][ni][r4];
                if (MODE == 3) {
                    if (m < M) split_store(val, oh, ol, (size_t)m * 1024 + n);
                } else if (MODE == 4) {
                    o0[(size_t)m * 1024 + n] = val + bias[n];
                } else if (MODE == 5) {
                    const int bh = blockIdx.z;
                    const int nb = bh >> 4, h = bh & 15;
                    split_store(val, oh, ol, ((size_t)nb * 1024 + m) * 1024 + h * 64 + n);
                } else {
                    val += bias[n];
                    const int nb = m >> 10, t = m & 1023;
                    const int h  = n >> 6,  dh = n & 63;
                    if (MODE == 0) {
                        const size_t idx = (((size_t)(nb * NH + h)) * TT + t) * DH + dh;
                        split_store(val + uu[n], oh,  ol,  idx);
                        split_store(val + vv[n], oh2, ol2, idx);
                    } else if (MODE == 1) {
                        const size_t idx = (((size_t)(nb * NH + h)) * TT + t) * DH + dh;
                        split_store(val, oh, ol, idx);
                    } else {   // MODE 2
                        const size_t idx = ((size_t)(nb * NH + h) * DH + dh) * TT + t;
                        split_store(val, oh, ol, idx);
                    }
                }
            }
}

// ---------------------------------------------------------------------------
// Tensor-core score kernel with rel-shift fused via fragment scatter.
// (unchanged from R9 — next profile decides its fate)
// ---------------------------------------------------------------------------
#define SMEM_SCORE 107520
__global__ __launch_bounds__(256, 2) void score_mma_kernel()
{
    extern __shared__ char smemc[];
    float* Ss = (float*)smemc;                      // [64][132]
    bf16* A0 = (bf16*)(smemc + 33792);              // plane stride 4608 (64x72)
    bf16* B0 = (bf16*)(smemc + 52224);              // p1 stride 13824 ; p2 9216

    const int tid = threadIdx.x;
    const int w = tid >> 5, lane = tid & 31;
    const int wm = w & 1, wn = w >> 1;              // 2 x 4 warps
    const int j0 = blockIdx.x * 128;
    const int i0 = blockIdx.y * 64;
    const int bh = blockIdx.z;
    const int h  = bh & 15;
    const int rb0 = i0 - j0 + 896;

    {
        const bf16* Qvp[2] = {g_Qvh, g_Qvl};
        #pragma unroll
        for (int p = 0; p < 2; p++)
            #pragma unroll
            for (int it = 0; it < 2; it++) {
                int id = tid + it * 256;
                int r = id >> 3, c8 = id & 7;
                *(uint4*)(A0 + p * 4608 + r * 72 + c8 * 8) =
                    *(const uint4*)(Qvp[p] + ((size_t)bh * 1024 + i0 + r) * 64 + c8 * 8);
            }
        const bf16* Rp[2] = {g_Rh, g_Rl};
        #pragma unroll
        for (int p = 0; p < 2; p++)
            #pragma unroll
            for (int it = 0; it < 6; it++) {
                int id = tid + it * 256;
                int r = id >> 3, c8 = id & 7;
                int grow = rb0 + r; if (grow > 2046) grow = 2046;
                *(uint4*)(B0 + p * 13824 + r * 72 + c8 * 8) =
                    *(const uint4*)(Rp[p] + (size_t)grow * 1024 + h * 64 + c8 * 8);
            }
    }
    __syncthreads();

    {
        float acc[2][6][4] = {};
        #pragma unroll
        for (int ks = 0; ks < 64; ks += 16) {
            uint32_t a[2][2][4];
            #pragma unroll
            for (int p = 0; p < 2; p++)
                #pragma unroll
                for (int mi = 0; mi < 2; mi++)
                    ldsm4(a[p][mi], smem_u32(A0 + p * 4608 +
                        (wm * 32 + mi * 16 + (lane & 15)) * 72 + ks + ((lane >> 4) << 3)));
            uint32_t b[2][6][2];
            #pragma unroll
            for (int p = 0; p < 2; p++)
                #pragma unroll
                for (int pr = 0; pr < 3; pr++) {
                    uint32_t t4[4];
                    ldsm4(t4, smem_u32(B0 + p * 13824 +
                        (wn * 48 + pr * 16 + (lane & 7) + ((lane >> 4) << 3)) * 72 +
                        ks + (((lane >> 3) & 1) << 3)));
                    b[p][2 * pr    ][0] = t4[0]; b[p][2 * pr    ][1] = t4[1];
                    b[p][2 * pr + 1][0] = t4[2]; b[p][2 * pr + 1][1] = t4[3];
                }
            #pragma unroll
            for (int mi = 0; mi < 2; mi++)
                #pragma unroll
                for (int ni = 0; ni < 6; ni++) {
                    mma16816(acc[mi][ni], a[0][mi], b[0][ni]);
                    mma16816(acc[mi][ni], a[0][mi], b[1][ni]);
                    mma16816(acc[mi][ni], a[1][mi], b[0][ni]);
                }
        }
        #pragma unroll
        for (int mi = 0; mi < 2; mi++)
            #pragma unroll
            for (int ni = 0; ni < 6; ni++)
                #pragma unroll
                for (int r4 = 0; r4 < 4; r4++) {
                    const int il = wm * 32 + mi * 16 + (lane >> 2) + ((r4 & 2) ? 8 : 0);
                    const int rl = wn * 48 + ni * 8 + ((lane & 3) << 1) + (r4 & 1);
                    const int jl = il - rl + 127;
                    if (jl >= 0 && jl < 128) Ss[il * 132 + jl] = acc[mi][ni][r4];
                }
    }
    __syncthreads();

    {
        const bf16* Qup[2] = {g_Quh, g_Qul};
        #pragma unroll
        for (int p = 0; p < 2; p++)
            #pragma unroll
            for (int it = 0; it < 2; it++) {
                int id = tid + it * 256;
                int r = id >> 3, c8 = id & 7;
                *(uint4*)(A0 + p * 4608 + r * 72 + c8 * 8) =
                    *(const uint4*)(Qup[p] + ((size_t)bh * 1024 + i0 + r) * 64 + c8 * 8);
            }
        const bf16* Kp[2] = {g_Kh, g_Kl};
        #pragma unroll
        for (int p = 0; p < 2; p++)
            #pragma unroll
            for (int it = 0; it < 4; it++) {
                int id = tid + it * 256;
                int r = id >> 3, c8 = id & 7;
                *(uint4*)(B0 + p * 9216 + r * 72 + c8 * 8) =
                    *(const uint4*)(Kp[p] + ((size_t)bh * 1024 + j0 + r) * 64 + c8 * 8);
            }
    }
    __syncthreads();

    {
        float acc[2][4][4] = {};
        #pragma unroll
        for (int ks = 0; ks < 64; ks += 16) {
            uint32_t a[2][2][4];
            #pragma unroll
            for (int p = 0; p < 2; p++)
                #pragma unroll
                for (int mi = 0; mi < 2; mi++)
                    ldsm4(a[p][mi], smem_u32(A0 + p * 4608 +
                        (wm * 32 + mi * 16 + (lane & 15)) * 72 + ks + ((lane >> 4) << 3)));
            uint32_t b[2][4][2];
            #pragma unroll
            for (int p = 0; p < 2; p++)
                #pragma unroll
                for (int pr = 0; pr < 2; pr++) {
                    uint32_t t4[4];
                    ldsm4(t4, smem_u32(B0 + p * 9216 +
                        (wn * 32 + pr * 16 + (lane & 7) + ((lane >> 4) << 3)) * 72 +
                        ks + (((lane >> 3) & 1) << 3)));
                    b[p][2 * pr    ][0] = t4[0]; b[p][2 * pr    ][1] = t4[1];
                    b[p][2 * pr + 1][0] = t4[2]; b[p][2 * pr + 1][1] = t4[3];
                }
            #pragma unroll
            for (int mi = 0; mi < 2; mi++)
                #pragma unroll
                for (int ni = 0; ni < 4; ni++) {
                    mma16816(acc[mi][ni], a[0][mi], b[0][ni]);
                    mma16816(acc[mi][ni], a[0][mi], b[1][ni]);
                    mma16816(acc[mi][ni], a[1][mi], b[0][ni]);
                }
        }
        float* Sp = g_S + ((size_t)bh << 20);
        #pragma unroll
        for (int mi = 0; mi < 2; mi++)
            #pragma unroll
            for (int ni = 0; ni < 4; ni++)
                #pragma unroll
                for (int r4 = 0; r4 < 4; r4++) {
                    const int il = wm * 32 + mi * 16 + (lane >> 2) + ((r4 & 2) ? 8 : 0);
                    const int jl = wn * 32 + ni * 8 + ((lane & 3) << 1) + (r4 & 1);
                    Sp[(size_t)(i0 + il) * 1024 + j0 + jl] =
                        acc[mi][ni][r4] + Ss[il * 132 + jl];
                }
    }
}

// ---------------------------------------------------------------------------
// Row softmax: float4 loads, shuffle reductions, bf162-packed plane stores.
// ---------------------------------------------------------------------------
__global__ __launch_bounds__(256) void softmax_kernel()
{
    const int row = blockIdx.x;
    const int tid = threadIdx.x;    // 256
    const float4* p4 = (const float4*)(g_S + (size_t)row * TT);
    float4 v = p4[tid];
    v.x *= 0.125f; v.y *= 0.125f; v.z *= 0.125f; v.w *= 0.125f;

    float m = fmaxf(fmaxf(v.x, v.y), fmaxf(v.z, v.w));
    #pragma unroll
    for (int o = 16; o; o >>= 1) m = fmaxf(m, __shfl_xor_sync(0xffffffffu, m, o));
    __shared__ float wm_[8], ws_[8];
    if ((tid & 31) == 0) wm_[tid >> 5] = m;
    __syncthreads();
    float mm = wm_[0];
    #pragma unroll
    for (int i = 1; i < 8; i++) mm = fmaxf(mm, wm_[i]);

    v.x = expf(v.x - mm); v.y = expf(v.y - mm);
    v.z = expf(v.z - mm); v.w = expf(v.w - mm);
    float s = v.x + v.y + v.z + v.w;
    #pragma unroll
    for (int o = 16; o; o >>= 1) s += __shfl_xor_sync(0xffffffffu, s, o);
    if ((tid & 31) == 0) ws_[tid >> 5] = s;
    __syncthreads();
    float sum = ws_[0];
    #pragma unroll
    for (int i = 1; i < 8; i++) sum += ws_[i];
    const float inv = 1.f / sum;

    float pv[4] = {v.x * inv, v.y * inv, v.z * inv, v.w * inv};
    bf16 hv[4], lv[4];
    #pragma unroll
    for (int q = 0; q < 4; q++) {
        hv[q] = __float2bfloat16(pv[q]);
        lv[q] = __float2bfloat16(pv[q] - __bfloat162float(hv[q]));
    }
    __nv_bfloat162* ph2 = (__nv_bfloat162*)(g_Ph + (size_t)row * TT);
    __nv_bfloat162* pl2 = (__nv_bfloat162*)(g_Pl + (size_t)row * TT);
    ph2[tid * 2 + 0] = __nv_bfloat162(hv[0], hv[1]);
    ph2[tid * 2 + 1] = __nv_bfloat162(hv[2], hv[3]);
    pl2[tid * 2 + 0] = __nv_bfloat162(lv[0], lv[1]);
    pl2[tid * 2 + 1] = __nv_bfloat162(lv[2], lv[3]);
}

// ---------------------------------------------------------------------------
extern "C" void kernel_launch(void* const* d_in, const int* in_sizes, int n_in,
                              void* d_out, int out_size)
{
    (void)in_sizes; (void)n_in; (void)out_size;
    const float* x      = (const float*)d_in[0];
    const float* rel_pe = (const float*)d_in[1];
    const float* Wq     = (const float*)d_in[2];
    const float* bq     = (const float*)d_in[3];
    const float* Wk     = (const float*)d_in[4];
    const float* bk     = (const float*)d_in[5];
    const float* Wv     = (const float*)d_in[6];
    const float* bv     = (const float*)d_in[7];
    const float* Wo     = (const float*)d_in[8];
    const float* bo     = (const float*)d_in[9];
    const float* Wr     = (const float*)d_in[10];
    const float* u      = (const float*)d_in[11];
    const float* v      = (const float*)d_in[12];
    float* out = (float*)d_out;

    bf16 *pxh, *pxl, *prh, *prl;
    bf16 *pwqh, *pwql, *pwkh, *pwkl, *pwvh, *pwvl, *pwrh, *pwrl, *pwoh, *pwol;
    bf16 *pQuh, *pQul, *pQvh, *pQvl, *pKh, *pKl, *pRh, *pRl;
    bf16 *pVh, *pVl, *pPh, *pPl, *pOh, *pOl;
    cudaGetSymbolAddress((void**)&pxh, g_xh);  cudaGetSymbolAddress((void**)&pxl, g_xl);
    cudaGetSymbolAddress((void**)&prh, g_rph); cudaGetSymbolAddress((void**)&prl, g_rpl);
    cudaGetSymbolAddress((void**)&pwqh, g_wqh); cudaGetSymbolAddress((void**)&pwql, g_wql);
    cudaGetSymbolAddress((void**)&pwkh, g_wkh); cudaGetSymbolAddress((void**)&pwkl, g_wkl);
    cudaGetSymbolAddress((void**)&pwvh, g_wvh); cudaGetSymbolAddress((void**)&pwvl, g_wvl);
    cudaGetSymbolAddress((void**)&pwrh, g_wrh); cudaGetSymbolAddress((void**)&pwrl, g_wrl);
    cudaGetSymbolAddress((void**)&pwoh, g_woh); cudaGetSymbolAddress((void**)&pwol, g_wol);
    cudaGetSymbolAddress((void**)&pQuh, g_Quh); cudaGetSymbolAddress((void**)&pQul, g_Qul);
    cudaGetSymbolAddress((void**)&pQvh, g_Qvh); cudaGetSymbolAddress((void**)&pQvl, g_Qvl);
    cudaGetSymbolAddress((void**)&pKh, g_Kh);  cudaGetSymbolAddress((void**)&pKl, g_Kl);
    cudaGetSymbolAddress((void**)&pRh, g_Rh);  cudaGetSymbolAddress((void**)&pRl, g_Rl);
    cudaGetSymbolAddress((void**)&pVh, g_Vh);  cudaGetSymbolAddress((void**)&pVl, g_Vl);
    cudaGetSymbolAddress((void**)&pPh, g_Ph);  cudaGetSymbolAddress((void**)&pPl, g_Pl);
    cudaGetSymbolAddress((void**)&pOh, g_Oh);  cudaGetSymbolAddress((void**)&pOl, g_Ol);

    const int SMEM_G128 = 2 * 2 * 128 * 40 * 2 * 2;   // 81920 B
    const int SMEM_G64  = 2 * 2 * 128 * 40 * 2 + 2 * 2 * 64 * 40 * 2; // 61440 B
    cudaFuncSetAttribute((const void*)mma_gemm<0,128,64,false>,
                         cudaFuncAttributeMaxDynamicSharedMemorySize, SMEM_G128);
    cudaFuncSetAttribute((const void*)mma_gemm<1,128,64,false>,
                         cudaFuncAttributeMaxDynamicSharedMemorySize, SMEM_G128);
    cudaFuncSetAttribute((const void*)mma_gemm<2,128,64,false>,
                         cudaFuncAttributeMaxDynamicSharedMemorySize, SMEM_G128);
    cudaFuncSetAttribute((const void*)mma_gemm<3,128,64,true>,
                         cudaFuncAttributeMaxDynamicSharedMemorySize, SMEM_G128);
    cudaFuncSetAttribute((const void*)mma_gemm<4,128,64,false>,
                         cudaFuncAttributeMaxDynamicSharedMemorySize, SMEM_G128);
    cudaFuncSetAttribute((const void*)mma_gemm<5,64,32,false>,
                         cudaFuncAttributeMaxDynamicSharedMemorySize, SMEM_G64);
    cudaFuncSetAttribute((const void*)score_mma_kernel,
                         cudaFuncAttributeMaxDynamicSharedMemorySize, SMEM_SCORE);

    const int NX = NB * TT * DM;
    const int NR = RLEN * DM;
    const int NW = DM * DM;

    // Launch order puts K-proj at slot #4 (ncu profiles launch #4).
    split_kernel<<<(NX + 255) / 256, 256>>>(x,      pxh,  pxl,  NX);   // 1
    split_kernel<<<(NW + 255) / 256, 256>>>(Wk,     pwkh, pwkl, NW);   // 2
    split_kernel<<<(NR + 255) / 256, 256>>>(rel_pe, prh,  prl,  NR);   // 3
    mma_gemm<1, 128, 64, false><<<dim3(32, 8), 256, SMEM_G128>>>(      // 4 (profiled)
        pxh, pxl, pwkh, pwkl, bk, nullptr, nullptr, nullptr, pKh, pKl, nullptr, nullptr, NB * TT);

    split_kernel<<<(NW + 255) / 256, 256>>>(Wq,     pwqh, pwql, NW);
    split_kernel<<<(NW + 255) / 256, 256>>>(Wv,     pwvh, pwvl, NW);
    split_kernel<<<(NW + 255) / 256, 256>>>(Wr,     pwrh, pwrl, NW);
    split_kernel<<<(NW + 255) / 256, 256>>>(Wo,     pwoh, pwol, NW);

    mma_gemm<0, 128, 64, false><<<dim3(32, 8), 256, SMEM_G128>>>(
        pxh, pxl, pwqh, pwql, bq, u, v, nullptr, pQuh, pQul, pQvh, pQvl, NB * TT);
    mma_gemm<2, 128, 64, false><<<dim3(32, 8), 256, SMEM_G128>>>(
        pxh, pxl, pwvh, pwvl, bv, nullptr, nullptr, nullptr, pVh, pVl, nullptr, nullptr, NB * TT);
    mma_gemm<3, 128, 64, true><<<dim3(16, 8), 256, SMEM_G128>>>(
        prh, prl, pwrh, pwrl, nullptr, nullptr, nullptr, nullptr, pRh, pRl, nullptr, nullptr, RLEN);

    score_mma_kernel<<<dim3(TT / 128, TT / 64, NB * NH), 256, SMEM_SCORE>>>();

    softmax_kernel<<<NB * NH * TT, 256>>>();

    mma_gemm<5, 64, 32, false><<<dim3(8, 1, NB * NH), 256, SMEM_G64>>>(
        pPh, pPl, pVh, pVl, nullptr, nullptr, nullptr, nullptr, pOh, pOl, nullptr, nullptr, TT);

    mma_gemm<4, 128, 64, false><<<dim3(32, 8), 256, SMEM_G128>>>(
        pOh, pOl, pwoh, pwol, bo, nullptr, nullptr, out, nullptr, nullptr, nullptr, nullptr, NB * TT);
}

// round 13
// speedup vs baseline: 3.6760x; 1.0373x over previous
#include <cuda_runtime.h>
#include <cuda_bf16.h>
#include <math.h>
#include <stdint.h>

#define NB      4
#define TT      1024
#define DM      1024
#define NH      16
#define DH      64
#define RLEN    2047   // 2*T - 1

typedef __nv_bfloat16 bf16;

// ---------------- fp32 scratch ----------------
__device__ float g_S [(size_t)NB*NH*TT*TT];     // scores (N,H,T,T)

// ---------------- bf16 split planes ----------------
__device__ bf16 g_xh [(size_t)NB*TT*DM],  g_xl [(size_t)NB*TT*DM];     // x
__device__ bf16 g_rph[(size_t)RLEN*DM],   g_rpl[(size_t)RLEN*DM];      // rel_pe
__device__ bf16 g_wqh[(size_t)DM*DM], g_wql[(size_t)DM*DM];
__device__ bf16 g_wkh[(size_t)DM*DM], g_wkl[(size_t)DM*DM];
__device__ bf16 g_wvh[(size_t)DM*DM], g_wvl[(size_t)DM*DM];
__device__ bf16 g_wrh[(size_t)DM*DM], g_wrl[(size_t)DM*DM];
__device__ bf16 g_woh[(size_t)DM*DM], g_wol[(size_t)DM*DM];
__device__ bf16 g_Quh[(size_t)NB*NH*TT*DH], g_Qul[(size_t)NB*NH*TT*DH]; // Q+u [bh][t][dh]
__device__ bf16 g_Qvh[(size_t)NB*NH*TT*DH], g_Qvl[(size_t)NB*NH*TT*DH]; // Q+v
__device__ bf16 g_Kh [(size_t)NB*NH*TT*DH], g_Kl [(size_t)NB*NH*TT*DH]; // K   [bh][t][dh]
__device__ bf16 g_Rh [(size_t)RLEN*DM],     g_Rl [(size_t)RLEN*DM];     // R   [r][D]
__device__ bf16 g_Vh [(size_t)NB*NH*DH*TT], g_Vl [(size_t)NB*NH*DH*TT]; // V   [bh][dh][t]
__device__ bf16 g_Ph [(size_t)NB*NH*TT*TT], g_Pl [(size_t)NB*NH*TT*TT]; // attn
__device__ bf16 g_Oh [(size_t)NB*TT*DM],    g_Ol [(size_t)NB*TT*DM];    // (N,T,D) concat

// ---------------------------------------------------------------------------
__device__ __forceinline__ uint32_t smem_u32(const void* p) {
    return (uint32_t)__cvta_generic_to_shared(p);
}
__device__ __forceinline__ void ldsm4(uint32_t* r, uint32_t addr) {
    asm volatile("ldmatrix.sync.aligned.m8n8.x4.shared.b16 {%0,%1,%2,%3}, [%4];"
                 : "=r"(r[0]), "=r"(r[1]), "=r"(r[2]), "=r"(r[3]) : "r"(addr));
}
__device__ __forceinline__ void mma16816(float* c, const uint32_t* a, const uint32_t* b) {
    asm volatile(
        "mma.sync.aligned.m16n8k16.row.col.f32.bf16.bf16.f32 "
        "{%0,%1,%2,%3}, {%4,%5,%6,%7}, {%8,%9}, {%0,%1,%2,%3};"
        : "+f"(c[0]), "+f"(c[1]), "+f"(c[2]), "+f"(c[3])
        : "r"(a[0]), "r"(a[1]), "r"(a[2]), "r"(a[3]), "r"(b[0]), "r"(b[1]));
}
__device__ __forceinline__ void split_store(float v, bf16* __restrict__ h,
                                            bf16* __restrict__ l, size_t idx) {
    bf16 hv = __float2bfloat16(v);
    h[idx] = hv;
    l[idx] = __float2bfloat16(v - __bfloat162float(hv));
}
__device__ __forceinline__ void cp16(const void* smem_ptr, const void* gptr, bool valid) {
    uint32_t sa = smem_u32(smem_ptr);
    int sz = valid ? 16 : 0;
    asm volatile("cp.async.cg.shared.global [%0], [%1], 16, %2;"
                 :: "r"(sa), "l"(gptr), "r"(sz) : "memory");
}

// ---------------------------------------------------------------------------
// split fp32 -> bf16 hi/lo planes
// ---------------------------------------------------------------------------
__global__ void split_kernel(const float* __restrict__ s,
                             bf16* __restrict__ h, bf16* __restrict__ l, int n)
{
    int i = blockIdx.x * 256 + threadIdx.x;
    if (i < n) split_store(s[i], h, l, i);
}

// ---------------------------------------------------------------------------
// bf16x3-split tensor-core GEMM with cp.async 2-stage pipeline.
// C = A(MxK) @ B^T, K=1024, B stored [n][k]. BM=128, BK=32, 256 threads.
// __launch_bounds__(256, 2) caps regs at 128 -> 2 CTAs/SM (occ 25%), and
// grid=256 then fits in ONE wave on 148 SMs.
// ---------------------------------------------------------------------------
template<int MODE, int BN, int WN, bool MG>
__global__ __launch_bounds__(256, 2) void mma_gemm(
    const bf16* __restrict__ Ah, const bf16* __restrict__ Al,
    const bf16* __restrict__ Bh, const bf16* __restrict__ Bl,
    const float* __restrict__ bias, const float* __restrict__ uu,
    const float* __restrict__ vv,
    float* __restrict__ o0,
    bf16* __restrict__ oh, bf16* __restrict__ ol,
    bf16* __restrict__ oh2, bf16* __restrict__ ol2, int M)
{
    constexpr int NN = WN / 8;
    extern __shared__ bf16 sm[];
    bf16* Asm = sm;                    // [(s*2+p)*128 + r]*40 + c
    bf16* Bsm = sm + 2 * 2 * 128 * 40; // [(s*2+p)*BN + r]*40 + c

    const int tid  = threadIdx.x;
    const int w    = tid >> 5, lane = tid & 31;
    const int wm   = w & 3,   wn   = w >> 2;
    const int m0   = blockIdx.x * 128, n0 = blockIdx.y * BN;

    const bf16* Aps[2] = {Ah, Al};
    const bf16* Bps[2] = {Bh, Bl};
    size_t abase = 0, bbase = 0;
    if (MODE == 5) { abase = (size_t)blockIdx.z << 20; bbase = (size_t)blockIdx.z << 16; }

    auto load_stage = [&](int s, int kk0) {
        #pragma unroll
        for (int it = 0; it < 4; it++) {            // A: 2p x 128r x 4 chunks
            int id = tid + it * 256;
            int p = id >> 9, rem = id & 511;
            int r = rem >> 2, c = rem & 3;
            bool ok = !MG || (m0 + r) < M;
            cp16(Asm + ((size_t)(s * 2 + p) * 128 + r) * 40 + c * 8,
                 Aps[p] + abase + (size_t)(m0 + r) * 1024 + kk0 + c * 8, ok);
        }
        #pragma unroll
        for (int it = 0; it < BN / 32; it++) {      // B: 2p x BNr x 4 chunks
            int id = tid + it * 256;
            int p = id / (4 * BN), rem = id % (4 * BN);
            int r = rem >> 2, c = rem & 3;
            cp16(Bsm + ((size_t)(s * 2 + p) * BN + r) * 40 + c * 8,
                 Bps[p] + bbase + (size_t)(n0 + r) * 1024 + kk0 + c * 8, true);
        }
        asm volatile("cp.async.commit_group;" ::: "memory");
    };

    float acc[2][NN][4] = {};

    load_stage(0, 0);
    for (int k0 = 0; k0 < 32; k0++) {
        if (k0 + 1 < 32) {
            load_stage((k0 + 1) & 1, (k0 + 1) * 32);
            asm volatile("cp.async.wait_group 1;" ::: "memory");
        } else {
            asm volatile("cp.async.wait_group 0;" ::: "memory");
        }
        __syncthreads();

        const int s = k0 & 1;
        const bf16* Ab = Asm + (size_t)(s * 2) * 128 * 40;
        const bf16* Bb = Bsm + (size_t)(s * 2) * BN * 40;

        #pragma unroll
        for (int ks = 0; ks < 32; ks += 16) {
            uint32_t a[2][2][4];
            #pragma unroll
            for (int p = 0; p < 2; p++)
                #pragma unroll
                for (int mi = 0; mi < 2; mi++)
                    ldsm4(a[p][mi], smem_u32(Ab + (size_t)p * 128 * 40 +
                        (wm * 32 + mi * 16 + (lane & 15)) * 40 + ks + ((lane >> 4) << 3)));
            uint32_t b[2][NN][2];
            #pragma unroll
            for (int p = 0; p < 2; p++)
                #pragma unroll
                for (int pr = 0; pr < NN / 2; pr++) {
                    uint32_t t4[4];
                    ldsm4(t4, smem_u32(Bb + (size_t)p * BN * 40 +
                        (wn * WN + pr * 16 + (lane & 7) + ((lane >> 4) << 3)) * 40 +
                        ks + (((lane >> 3) & 1) << 3)));
                    b[p][2 * pr    ][0] = t4[0]; b[p][2 * pr    ][1] = t4[1];
                    b[p][2 * pr + 1][0] = t4[2]; b[p][2 * pr + 1][1] = t4[3];
                }
            #pragma unroll
            for (int mi = 0; mi < 2; mi++)
                #pragma unroll
                for (int ni = 0; ni < NN; ni++) {
                    mma16816(acc[mi][ni], a[0][mi], b[0][ni]);   // hi*hi
                    mma16816(acc[mi][ni], a[0][mi], b[1][ni]);   // hi*lo
                    mma16816(acc[mi][ni], a[1][mi], b[0][ni]);   // lo*hi
                }
        }
        __syncthreads();
    }

    // ---- epilogue ----
    #pragma unroll
    for (int mi = 0; mi < 2; mi++)
        #pragma unroll
        for (int ni = 0; ni < NN; ni++)
            #pragma unroll
            for (int r4 = 0; r4 < 4; r4++) {
                const int m = m0 + wm * 32 + mi * 16 + (lane >> 2) + ((r4 & 2) ? 8 : 0);
                const int n = n0 + wn * WN + ni * 8 + ((lane & 3) << 1) + (r4 & 1);
                float val = acc[mi][ni][r4];
                if (MODE == 3) {
                    if (m < M) split_store(val, oh, ol, (size_t)m * 1024 + n);
                } else if (MODE == 4) {
                    o0[(size_t)m * 1024 + n] = val + bias[n];
                } else if (MODE == 5) {
                    const int bh = blockIdx.z;
                    const int nb = bh >> 4, h = bh & 15;
                    split_store(val, oh, ol, ((size_t)nb * 1024 + m) * 1024 + h * 64 + n);
                } else {
                    val += bias[n];
                    const int nb = m >> 10, t = m & 1023;
                    const int h  = n >> 6,  dh = n & 63;
                    if (MODE == 0) {
                        const size_t idx = (((size_t)(nb * NH + h)) * TT + t) * DH + dh;
                        split_store(val + uu[n], oh,  ol,  idx);
                        split_store(val + vv[n], oh2, ol2, idx);
                    } else if (MODE == 1) {
                        const size_t idx = (((size_t)(nb * NH + h)) * TT + t) * DH + dh;
                        split_store(val, oh, ol, idx);
                    } else {   // MODE 2
                        const size_t idx = ((size_t)(nb * NH + h) * DH + dh) * TT + t;
                        split_store(val, oh, ol, idx);
                    }
                }
            }
}

// ---------------------------------------------------------------------------
// Tensor-core score kernel with rel-shift fused via fragment scatter.
// ---------------------------------------------------------------------------
#define SMEM_SCORE 107520
__global__ __launch_bounds__(256, 2) void score_mma_kernel()
{
    extern __shared__ char smemc[];
    float* Ss = (float*)smemc;                      // [64][132]
    bf16* A0 = (bf16*)(smemc + 33792);              // plane stride 4608 (64x72)
    bf16* B0 = (bf16*)(smemc + 52224);              // p1 stride 13824 ; p2 9216

    const int tid = threadIdx.x;
    const int w = tid >> 5, lane = tid & 31;
    const int wm = w & 1, wn = w >> 1;              // 2 x 4 warps
    const int j0 = blockIdx.x * 128;
    const int i0 = blockIdx.y * 64;
    const int bh = blockIdx.z;
    const int h  = bh & 15;
    const int rb0 = i0 - j0 + 896;

    {
        const bf16* Qvp[2] = {g_Qvh, g_Qvl};
        #pragma unroll
        for (int p = 0; p < 2; p++)
            #pragma unroll
            for (int it = 0; it < 2; it++) {
                int id = tid + it * 256;
                int r = id >> 3, c8 = id & 7;
                *(uint4*)(A0 + p * 4608 + r * 72 + c8 * 8) =
                    *(const uint4*)(Qvp[p] + ((size_t)bh * 1024 + i0 + r) * 64 + c8 * 8);
            }
        const bf16* Rp[2] = {g_Rh, g_Rl};
        #pragma unroll
        for (int p = 0; p < 2; p++)
            #pragma unroll
            for (int it = 0; it < 6; it++) {
                int id = tid + it * 256;
                int r = id >> 3, c8 = id & 7;
                int grow = rb0 + r; if (grow > 2046) grow = 2046;
                *(uint4*)(B0 + p * 13824 + r * 72 + c8 * 8) =
                    *(const uint4*)(Rp[p] + (size_t)grow * 1024 + h * 64 + c8 * 8);
            }
    }
    __syncthreads();

    {
        float acc[2][6][4] = {};
        #pragma unroll
        for (int ks = 0; ks < 64; ks += 16) {
            uint32_t a[2][2][4];
            #pragma unroll
            for (int p = 0; p < 2; p++)
                #pragma unroll
                for (int mi = 0; mi < 2; mi++)
                    ldsm4(a[p][mi], smem_u32(A0 + p * 4608 +
                        (wm * 32 + mi * 16 + (lane & 15)) * 72 + ks + ((lane >> 4) << 3)));
            uint32_t b[2][6][2];
            #pragma unroll
            for (int p = 0; p < 2; p++)
                #pragma unroll
                for (int pr = 0; pr < 3; pr++) {
                    uint32_t t4[4];
                    ldsm4(t4, smem_u32(B0 + p * 13824 +
                        (wn * 48 + pr * 16 + (lane & 7) + ((lane >> 4) << 3)) * 72 +
                        ks + (((lane >> 3) & 1) << 3)));
                    b[p][2 * pr    ][0] = t4[0]; b[p][2 * pr    ][1] = t4[1];
                    b[p][2 * pr + 1][0] = t4[2]; b[p][2 * pr + 1][1] = t4[3];
                }
            #pragma unroll
            for (int mi = 0; mi < 2; mi++)
                #pragma unroll
                for (int ni = 0; ni < 6; ni++) {
                    mma16816(acc[mi][ni], a[0][mi], b[0][ni]);
                    mma16816(acc[mi][ni], a[0][mi], b[1][ni]);
                    mma16816(acc[mi][ni], a[1][mi], b[0][ni]);
                }
        }
        #pragma unroll
        for (int mi = 0; mi < 2; mi++)
            #pragma unroll
            for (int ni = 0; ni < 6; ni++)
                #pragma unroll
                for (int r4 = 0; r4 < 4; r4++) {
                    const int il = wm * 32 + mi * 16 + (lane >> 2) + ((r4 & 2) ? 8 : 0);
                    const int rl = wn * 48 + ni * 8 + ((lane & 3) << 1) + (r4 & 1);
                    const int jl = il - rl + 127;
                    if (jl >= 0 && jl < 128) Ss[il * 132 + jl] = acc[mi][ni][r4];
                }
    }
    __syncthreads();

    {
        const bf16* Qup[2] = {g_Quh, g_Qul};
        #pragma unroll
        for (int p = 0; p < 2; p++)
            #pragma unroll
            for (int it = 0; it < 2; it++) {
                int id = tid + it * 256;
                int r = id >> 3, c8 = id & 7;
                *(uint4*)(A0 + p * 4608 + r * 72 + c8 * 8) =
                    *(const uint4*)(Qup[p] + ((size_t)bh * 1024 + i0 + r) * 64 + c8 * 8);
            }
        const bf16* Kp[2] = {g_Kh, g_Kl};
        #pragma unroll
        for (int p = 0; p < 2; p++)
            #pragma unroll
            for (int it = 0; it < 4; it++) {
                int id = tid + it * 256;
                int r = id >> 3, c8 = id & 7;
                *(uint4*)(B0 + p * 9216 + r * 72 + c8 * 8) =
                    *(const uint4*)(Kp[p] + ((size_t)bh * 1024 + j0 + r) * 64 + c8 * 8);
            }
    }
    __syncthreads();

    {
        float acc[2][4][4] = {};
        #pragma unroll
        for (int ks = 0; ks < 64; ks += 16) {
            uint32_t a[2][2][4];
            #pragma unroll
            for (int p = 0; p < 2; p++)
                #pragma unroll
                for (int mi = 0; mi < 2; mi++)
                    ldsm4(a[p][mi], smem_u32(A0 + p * 4608 +
                        (wm * 32 + mi * 16 + (lane & 15)) * 72 + ks + ((lane >> 4) << 3)));
            uint32_t b[2][4][2];
            #pragma unroll
            for (int p = 0; p < 2; p++)
                #pragma unroll
                for (int pr = 0; pr < 2; pr++) {
                    uint32_t t4[4];
                    ldsm4(t4, smem_u32(B0 + p * 9216 +
                        (wn * 32 + pr * 16 + (lane & 7) + ((lane >> 4) << 3)) * 72 +
                        ks + (((lane >> 3) & 1) << 3)));
                    b[p][2 * pr    ][0] = t4[0]; b[p][2 * pr    ][1] = t4[1];
                    b[p][2 * pr + 1][0] = t4[2]; b[p][2 * pr + 1][1] = t4[3];
                }
            #pragma unroll
            for (int mi = 0; mi < 2; mi++)
                #pragma unroll
                for (int ni = 0; ni < 4; ni++) {
                    mma16816(acc[mi][ni], a[0][mi], b[0][ni]);
                    mma16816(acc[mi][ni], a[0][mi], b[1][ni]);
                    mma16816(acc[mi][ni], a[1][mi], b[0][ni]);
                }
        }
        float* Sp = g_S + ((size_t)bh << 20);
        #pragma unroll
        for (int mi = 0; mi < 2; mi++)
            #pragma unroll
            for (int ni = 0; ni < 4; ni++)
                #pragma unroll
                for (int r4 = 0; r4 < 4; r4++) {
                    const int il = wm * 32 + mi * 16 + (lane >> 2) + ((r4 & 2) ? 8 : 0);
                    const int jl = wn * 32 + ni * 8 + ((lane & 3) << 1) + (r4 & 1);
                    Sp[(size_t)(i0 + il) * 1024 + j0 + jl] =
                        acc[mi][ni][r4] + Ss[il * 132 + jl];
                }
    }
}

// ---------------------------------------------------------------------------
// Row softmax: float4 loads, shuffle reductions, bf162-packed plane stores.
// ---------------------------------------------------------------------------
__global__ __launch_bounds__(256) void softmax_kernel()
{
    const int row = blockIdx.x;
    const int tid = threadIdx.x;    // 256
    const float4* p4 = (const float4*)(g_S + (size_t)row * TT);
    float4 v = p4[tid];
    v.x *= 0.125f; v.y *= 0.125f; v.z *= 0.125f; v.w *= 0.125f;

    float m = fmaxf(fmaxf(v.x, v.y), fmaxf(v.z, v.w));
    #pragma unroll
    for (int o = 16; o; o >>= 1) m = fmaxf(m, __shfl_xor_sync(0xffffffffu, m, o));
    __shared__ float wm_[8], ws_[8];
    if ((tid & 31) == 0) wm_[tid >> 5] = m;
    __syncthreads();
    float mm = wm_[0];
    #pragma unroll
    for (int i = 1; i < 8; i++) mm = fmaxf(mm, wm_[i]);

    v.x = expf(v.x - mm); v.y = expf(v.y - mm);
    v.z = expf(v.z - mm); v.w = expf(v.w - mm);
    float s = v.x + v.y + v.z + v.w;
    #pragma unroll
    for (int o = 16; o; o >>= 1) s += __shfl_xor_sync(0xffffffffu, s, o);
    if ((tid & 31) == 0) ws_[tid >> 5] = s;
    __syncthreads();
    float sum = ws_[0];
    #pragma unroll
    for (int i = 1; i < 8; i++) sum += ws_[i];
    const float inv = 1.f / sum;

    float pv[4] = {v.x * inv, v.y * inv, v.z * inv, v.w * inv};
    bf16 hv[4], lv[4];
    #pragma unroll
    for (int q = 0; q < 4; q++) {
        hv[q] = __float2bfloat16(pv[q]);
        lv[q] = __float2bfloat16(pv[q] - __bfloat162float(hv[q]));
    }
    __nv_bfloat162* ph2 = (__nv_bfloat162*)(g_Ph + (size_t)row * TT);
    __nv_bfloat162* pl2 = (__nv_bfloat162*)(g_Pl + (size_t)row * TT);
    ph2[tid * 2 + 0] = __nv_bfloat162(hv[0], hv[1]);
    ph2[tid * 2 + 1] = __nv_bfloat162(hv[2], hv[3]);
    pl2[tid * 2 + 0] = __nv_bfloat162(lv[0], lv[1]);
    pl2[tid * 2 + 1] = __nv_bfloat162(lv[2], lv[3]);
}

// ---------------------------------------------------------------------------
extern "C" void kernel_launch(void* const* d_in, const int* in_sizes, int n_in,
                              void* d_out, int out_size)
{
    (void)in_sizes; (void)n_in; (void)out_size;
    const float* x      = (const float*)d_in[0];
    const float* rel_pe = (const float*)d_in[1];
    const float* Wq     = (const float*)d_in[2];
    const float* bq     = (const float*)d_in[3];
    const float* Wk     = (const float*)d_in[4];
    const float* bk     = (const float*)d_in[5];
    const float* Wv     = (const float*)d_in[6];
    const float* bv     = (const float*)d_in[7];
    const float* Wo     = (const float*)d_in[8];
    const float* bo     = (const float*)d_in[9];
    const float* Wr     = (const float*)d_in[10];
    const float* u      = (const float*)d_in[11];
    const float* v      = (const float*)d_in[12];
    float* out = (float*)d_out;

    bf16 *pxh, *pxl, *prh, *prl;
    bf16 *pwqh, *pwql, *pwkh, *pwkl, *pwvh, *pwvl, *pwrh, *pwrl, *pwoh, *pwol;
    bf16 *pQuh, *pQul, *pQvh, *pQvl, *pKh, *pKl, *pRh, *pRl;
    bf16 *pVh, *pVl, *pPh, *pPl, *pOh, *pOl;
    cudaGetSymbolAddress((void**)&pxh, g_xh);  cudaGetSymbolAddress((void**)&pxl, g_xl);
    cudaGetSymbolAddress((void**)&prh, g_rph); cudaGetSymbolAddress((void**)&prl, g_rpl);
    cudaGetSymbolAddress((void**)&pwqh, g_wqh); cudaGetSymbolAddress((void**)&pwql, g_wql);
    cudaGetSymbolAddress((void**)&pwkh, g_wkh); cudaGetSymbolAddress((void**)&pwkl, g_wkl);
    cudaGetSymbolAddress((void**)&pwvh, g_wvh); cudaGetSymbolAddress((void**)&pwvl, g_wvl);
    cudaGetSymbolAddress((void**)&pwrh, g_wrh); cudaGetSymbolAddress((void**)&pwrl, g_wrl);
    cudaGetSymbolAddress((void**)&pwoh, g_woh); cudaGetSymbolAddress((void**)&pwol, g_wol);
    cudaGetSymbolAddress((void**)&pQuh, g_Quh); cudaGetSymbolAddress((void**)&pQul, g_Qul);
    cudaGetSymbolAddress((void**)&pQvh, g_Qvh); cudaGetSymbolAddress((void**)&pQvl, g_Qvl);
    cudaGetSymbolAddress((void**)&pKh, g_Kh);  cudaGetSymbolAddress((void**)&pKl, g_Kl);
    cudaGetSymbolAddress((void**)&pRh, g_Rh);  cudaGetSymbolAddress((void**)&pRl, g_Rl);
    cudaGetSymbolAddress((void**)&pVh, g_Vh);  cudaGetSymbolAddress((void**)&pVl, g_Vl);
    cudaGetSymbolAddress((void**)&pPh, g_Ph);  cudaGetSymbolAddress((void**)&pPl, g_Pl);
    cudaGetSymbolAddress((void**)&pOh, g_Oh);  cudaGetSymbolAddress((void**)&pOl, g_Ol);

    const int SMEM_G128 = 2 * 2 * 128 * 40 * 2 * 2;   // 81920 B
    const int SMEM_G64  = 2 * 2 * 128 * 40 * 2 + 2 * 2 * 64 * 40 * 2; // 61440 B
    cudaFuncSetAttribute((const void*)mma_gemm<0,128,64,false>,
                         cudaFuncAttributeMaxDynamicSharedMemorySize, SMEM_G128);
    cudaFuncSetAttribute((const void*)mma_gemm<1,128,64,false>,
                         cudaFuncAttributeMaxDynamicSharedMemorySize, SMEM_G128);
    cudaFuncSetAttribute((const void*)mma_gemm<2,128,64,false>,
                         cudaFuncAttributeMaxDynamicSharedMemorySize, SMEM_G128);
    cudaFuncSetAttribute((const void*)mma_gemm<3,128,64,true>,
                         cudaFuncAttributeMaxDynamicSharedMemorySize, SMEM_G128);
    cudaFuncSetAttribute((const void*)mma_gemm<4,128,64,false>,
                         cudaFuncAttributeMaxDynamicSharedMemorySize, SMEM_G128);
    cudaFuncSetAttribute((const void*)mma_gemm<5,64,32,false>,
                         cudaFuncAttributeMaxDynamicSharedMemorySize, SMEM_G64);
    cudaFuncSetAttribute((const void*)score_mma_kernel,
                         cudaFuncAttributeMaxDynamicSharedMemorySize, SMEM_SCORE);

    const int NX = NB * TT * DM;
    const int NR = RLEN * DM;
    const int NW = DM * DM;

    // Launch order keeps K-proj at slot #4 (ncu profiles launch #4) to verify
    // the occupancy fix directly.
    split_kernel<<<(NX + 255) / 256, 256>>>(x,      pxh,  pxl,  NX);   // 1
    split_kernel<<<(NW + 255) / 256, 256>>>(Wk,     pwkh, pwkl, NW);   // 2
    split_kernel<<<(NR + 255) / 256, 256>>>(rel_pe, prh,  prl,  NR);   // 3
    mma_gemm<1, 128, 64, false><<<dim3(32, 8), 256, SMEM_G128>>>(      // 4 (profiled)
        pxh, pxl, pwkh, pwkl, bk, nullptr, nullptr, nullptr, pKh, pKl, nullptr, nullptr, NB * TT);

    split_kernel<<<(NW + 255) / 256, 256>>>(Wq,     pwqh, pwql, NW);
    split_kernel<<<(NW + 255) / 256, 256>>>(Wv,     pwvh, pwvl, NW);
    split_kernel<<<(NW + 255) / 256, 256>>>(Wr,     pwrh, pwrl, NW);
    split_kernel<<<(NW + 255) / 256, 256>>>(Wo,     pwoh, pwol, NW);

    mma_gemm<0, 128, 64, false><<<dim3(32, 8), 256, SMEM_G128>>>(
        pxh, pxl, pwqh, pwql, bq, u, v, nullptr, pQuh, pQul, pQvh, pQvl, NB * TT);
    mma_gemm<2, 128, 64, false><<<dim3(32, 8), 256, SMEM_G128>>>(
        pxh, pxl, pwvh, pwvl, bv, nullptr, nullptr, nullptr, pVh, pVl, nullptr, nullptr, NB * TT);
    mma_gemm<3, 128, 64, true><<<dim3(16, 8), 256, SMEM_G128>>>(
        prh, prl, pwrh, pwrl, nullptr, nullptr, nullptr, nullptr, pRh, pRl, nullptr, nullptr, RLEN);

    score_mma_kernel<<<dim3(TT / 128, TT / 64, NB * NH), 256, SMEM_SCORE>>>();

    softmax_kernel<<<NB * NH * TT, 256>>>();

    mma_gemm<5, 64, 32, false><<<dim3(8, 1, NB * NH), 256, SMEM_G64>>>(
        pPh, pPl, pVh, pVl, nullptr, nullptr, nullptr, nullptr, pOh, pOl, nullptr, nullptr, TT);

    mma_gemm<4, 128, 64, false><<<dim3(32, 8), 256, SMEM_G128>>>(
        pOh, pOl, pwoh, pwol, bo, nullptr, nullptr, out, nullptr, nullptr, nullptr, nullptr, NB * TT);
}

// round 14
// speedup vs baseline: 3.7842x; 1.0294x over previous
#include <cuda_runtime.h>
#include <cuda_bf16.h>
#include <math.h>
#include <stdint.h>

#define NB      4
#define TT      1024
#define DM      1024
#define NH      16
#define DH      64
#define RLEN    2047   // 2*T - 1

typedef __nv_bfloat16 bf16;

// ---------------- fp32 scratch ----------------
__device__ float g_S [(size_t)NB*NH*TT*TT];     // scores (N,H,T,T)

// ---------------- bf16 split planes ----------------
__device__ bf16 g_xh [(size_t)NB*TT*DM],  g_xl [(size_t)NB*TT*DM];     // x
__device__ bf16 g_rph[(size_t)RLEN*DM],   g_rpl[(size_t)RLEN*DM];      // rel_pe
__device__ bf16 g_wqh[(size_t)DM*DM], g_wql[(size_t)DM*DM];
__device__ bf16 g_wkh[(size_t)DM*DM], g_wkl[(size_t)DM*DM];
__device__ bf16 g_wvh[(size_t)DM*DM], g_wvl[(size_t)DM*DM];
__device__ bf16 g_wrh[(size_t)DM*DM], g_wrl[(size_t)DM*DM];
__device__ bf16 g_woh[(size_t)DM*DM], g_wol[(size_t)DM*DM];
__device__ bf16 g_Quh[(size_t)NB*NH*TT*DH], g_Qul[(size_t)NB*NH*TT*DH]; // Q+u [bh][t][dh]
__device__ bf16 g_Qvh[(size_t)NB*NH*TT*DH], g_Qvl[(size_t)NB*NH*TT*DH]; // Q+v
__device__ bf16 g_Kh [(size_t)NB*NH*TT*DH], g_Kl [(size_t)NB*NH*TT*DH]; // K   [bh][t][dh]
__device__ bf16 g_Rh [(size_t)RLEN*DM],     g_Rl [(size_t)RLEN*DM];     // R   [r][D]
__device__ bf16 g_Vh [(size_t)NB*NH*DH*TT], g_Vl [(size_t)NB*NH*DH*TT]; // V   [bh][dh][t]
__device__ bf16 g_Ph [(size_t)NB*NH*TT*TT], g_Pl [(size_t)NB*NH*TT*TT]; // attn
__device__ bf16 g_Oh [(size_t)NB*TT*DM],    g_Ol [(size_t)NB*TT*DM];    // (N,T,D) concat

// ---------------------------------------------------------------------------
__device__ __forceinline__ uint32_t smem_u32(const void* p) {
    return (uint32_t)__cvta_generic_to_shared(p);
}
__device__ __forceinline__ void ldsm4(uint32_t* r, uint32_t addr) {
    asm volatile("ldmatrix.sync.aligned.m8n8.x4.shared.b16 {%0,%1,%2,%3}, [%4];"
                 : "=r"(r[0]), "=r"(r[1]), "=r"(r[2]), "=r"(r[3]) : "r"(addr));
}
__device__ __forceinline__ void mma16816(float* c, const uint32_t* a, const uint32_t* b) {
    asm volatile(
        "mma.sync.aligned.m16n8k16.row.col.f32.bf16.bf16.f32 "
        "{%0,%1,%2,%3}, {%4,%5,%6,%7}, {%8,%9}, {%0,%1,%2,%3};"
        : "+f"(c[0]), "+f"(c[1]), "+f"(c[2]), "+f"(c[3])
        : "r"(a[0]), "r"(a[1]), "r"(a[2]), "r"(a[3]), "r"(b[0]), "r"(b[1]));
}
__device__ __forceinline__ void split_store(float v, bf16* __restrict__ h,
                                            bf16* __restrict__ l, size_t idx) {
    bf16 hv = __float2bfloat16(v);
    h[idx] = hv;
    l[idx] = __float2bfloat16(v - __bfloat162float(hv));
}
__device__ __forceinline__ void cp16(const void* smem_ptr, const void* gptr, bool valid) {
    uint32_t sa = smem_u32(smem_ptr);
    int sz = valid ? 16 : 0;
    asm volatile("cp.async.cg.shared.global [%0], [%1], 16, %2;"
                 :: "r"(sa), "l"(gptr), "r"(sz) : "memory");
}

// ---------------------------------------------------------------------------
// split kernels: fp32 -> bf16 hi/lo planes
// ---------------------------------------------------------------------------
__global__ void split_kernel(const float* __restrict__ s,
                             bf16* __restrict__ h, bf16* __restrict__ l, int n)
{
    int i = blockIdx.x * 256 + threadIdx.x;
    if (i < n) split_store(s[i], h, l, i);
}

// combined split of Wq, Wk, Wv (3 x 1M elements) in one launch
__global__ void split3_kernel(const float* __restrict__ s0, const float* __restrict__ s1,
                              const float* __restrict__ s2)
{
    const int NW = DM * DM;
    int i = blockIdx.x * 256 + threadIdx.x;
    if (i < NW)            split_store(s0[i],          g_wqh, g_wql, i);
    else if (i < 2 * NW)   split_store(s1[i - NW],     g_wkh, g_wkl, i - NW);
    else if (i < 3 * NW)   split_store(s2[i - 2 * NW], g_wvh, g_wvl, i - 2 * NW);
}

// ---------------------------------------------------------------------------
// Shared bf16x3-split mainloop: C = A(128xK) @ B(BN x K)^T, K=1024.
// 2-stage cp.async pipeline; per-ks the three split terms are INTERLEAVED
// with their fragment loads so LDS and tensor pipes overlap:
//   ld a0,b0 -> mma hi*hi -> ld b1 -> mma hi*lo -> ld a1 -> mma lo*hi
// ---------------------------------------------------------------------------
template<int BN, int NN, bool MG>
__device__ __forceinline__ void mainloop(
    const bf16* __restrict__ Ah, const bf16* __restrict__ Al,
    const bf16* __restrict__ Bh, const bf16* __restrict__ Bl,
    size_t abase, size_t bbase, int m0, int n0, int M,
    float acc[2][NN][4])
{
    constexpr int WN = NN * 8;
    extern __shared__ bf16 sm[];
    bf16* Asm = sm;                    // [(s*2+p)*128 + r]*40 + c
    bf16* Bsm = sm + 2 * 2 * 128 * 40; // [(s*2+p)*BN + r]*40 + c

    const int tid  = threadIdx.x;
    const int w    = tid >> 5, lane = tid & 31;
    const int wm   = w & 3,   wn   = w >> 2;

    const bf16* Aps[2] = {Ah, Al};
    const bf16* Bps[2] = {Bh, Bl};

    auto load_stage = [&](int s, int kk0) {
        #pragma unroll
        for (int it = 0; it < 4; it++) {            // A: 2p x 128r x 4 chunks
            int id = tid + it * 256;
            int p = id >> 9, rem = id & 511;
            int r = rem >> 2, c = rem & 3;
            bool ok = !MG || (m0 + r) < M;
            cp16(Asm + ((size_t)(s * 2 + p) * 128 + r) * 40 + c * 8,
                 Aps[p] + abase + (size_t)(m0 + r) * 1024 + kk0 + c * 8, ok);
        }
        #pragma unroll
        for (int it = 0; it < BN / 32; it++) {      // B: 2p x BNr x 4 chunks
            int id = tid + it * 256;
            int p = id / (4 * BN), rem = id % (4 * BN);
            int r = rem >> 2, c = rem & 3;
            cp16(Bsm + ((size_t)(s * 2 + p) * BN + r) * 40 + c * 8,
                 Bps[p] + bbase + (size_t)(n0 + r) * 1024 + kk0 + c * 8, true);
        }
        asm volatile("cp.async.commit_group;" ::: "memory");
    };

    load_stage(0, 0);
    for (int k0 = 0; k0 < 32; k0++) {
        if (k0 + 1 < 32) {
            load_stage((k0 + 1) & 1, (k0 + 1) * 32);
            asm volatile("cp.async.wait_group 1;" ::: "memory");
        } else {
            asm volatile("cp.async.wait_group 0;" ::: "memory");
        }
        __syncthreads();

        const int s = k0 & 1;
        const bf16* Ab = Asm + (size_t)(s * 2) * 128 * 40;
        const bf16* Bb = Bsm + (size_t)(s * 2) * BN * 40;

        #pragma unroll
        for (int ks = 0; ks < 32; ks += 16) {
            uint32_t a0[2][4], a1[2][4], b0[NN][2], b1[NN][2];

            // hi fragments
            #pragma unroll
            for (int mi = 0; mi < 2; mi++)
                ldsm4(a0[mi], smem_u32(Ab +
                    (wm * 32 + mi * 16 + (lane & 15)) * 40 + ks + ((lane >> 4) << 3)));
            #pragma unroll
            for (int pr = 0; pr < NN / 2; pr++) {
                uint32_t t4[4];
                ldsm4(t4, smem_u32(Bb +
                    (wn * WN + pr * 16 + (lane & 7) + ((lane >> 4) << 3)) * 40 +
                    ks + (((lane >> 3) & 1) << 3)));
                b0[2 * pr    ][0] = t4[0]; b0[2 * pr    ][1] = t4[1];
                b0[2 * pr + 1][0] = t4[2]; b0[2 * pr + 1][1] = t4[3];
            }
            // hi*hi
            #pragma unroll
            for (int mi = 0; mi < 2; mi++)
                #pragma unroll
                for (int ni = 0; ni < NN; ni++)
                    mma16816(acc[mi][ni], a0[mi], b0[ni]);
            // lo-B fragments
            #pragma unroll
            for (int pr = 0; pr < NN / 2; pr++) {
                uint32_t t4[4];
                ldsm4(t4, smem_u32(Bb + (size_t)BN * 40 +
                    (wn * WN + pr * 16 + (lane & 7) + ((lane >> 4) << 3)) * 40 +
                    ks + (((lane >> 3) & 1) << 3)));
                b1[2 * pr    ][0] = t4[0]; b1[2 * pr    ][1] = t4[1];
                b1[2 * pr + 1][0] = t4[2]; b1[2 * pr + 1][1] = t4[3];
            }
            // hi*lo
            #pragma unroll
            for (int mi = 0; mi < 2; mi++)
                #pragma unroll
                for (int ni = 0; ni < NN; ni++)
                    mma16816(acc[mi][ni], a0[mi], b1[ni]);
            // lo-A fragments
            #pragma unroll
            for (int mi = 0; mi < 2; mi++)
                ldsm4(a1[mi], smem_u32(Ab + (size_t)128 * 40 +
                    (wm * 32 + mi * 16 + (lane & 15)) * 40 + ks + ((lane >> 4) << 3)));
            // lo*hi
            #pragma unroll
            for (int mi = 0; mi < 2; mi++)
                #pragma unroll
                for (int ni = 0; ni < NN; ni++)
                    mma16816(acc[mi][ni], a1[mi], b0[ni]);
        }
        __syncthreads();
    }
}

// ---------------------------------------------------------------------------
// Fused Q/K/V projection GEMM. grid (32, 24): seg = y>>3 (0=Q,1=K,2=V),
// n0 = (y&7)*128. Reads x and weight planes from globals.
// ---------------------------------------------------------------------------
__global__ __launch_bounds__(256, 2) void qkv_gemm(
    const float* __restrict__ bq, const float* __restrict__ bk,
    const float* __restrict__ bv, const float* __restrict__ uu,
    const float* __restrict__ vv)
{
    const int seg = blockIdx.y >> 3;
    const int n0 = (blockIdx.y & 7) * 128;
    const int m0 = blockIdx.x * 128;
    const bf16* Bh = seg == 0 ? g_wqh : seg == 1 ? g_wkh : g_wvh;
    const bf16* Bl = seg == 0 ? g_wql : seg == 1 ? g_wkl : g_wvl;
    const float* bias = seg == 0 ? bq : seg == 1 ? bk : bv;

    float acc[2][8][4] = {};
    mainloop<128, 8, false>(g_xh, g_xl, Bh, Bl, 0, 0, m0, n0, 0, acc);

    const int lane = threadIdx.x & 31;
    const int w = threadIdx.x >> 5;
    const int wm = w & 3, wn = w >> 2;
    #pragma unroll
    for (int mi = 0; mi < 2; mi++)
        #pragma unroll
        for (int ni = 0; ni < 8; ni++)
            #pragma unroll
            for (int r4 = 0; r4 < 4; r4++) {
                const int m = m0 + wm * 32 + mi * 16 + (lane >> 2) + ((r4 & 2) ? 8 : 0);
                const int n = n0 + wn * 64 + ni * 8 + ((lane & 3) << 1) + (r4 & 1);
                float val = acc[mi][ni][r4] + bias[n];
                const int nb = m >> 10, t = m & 1023;
                const int h  = n >> 6,  dh = n & 63;
                if (seg == 0) {
                    const size_t idx = (((size_t)(nb * NH + h)) * TT + t) * DH + dh;
                    split_store(val + uu[n], g_Quh, g_Qul, idx);
                    split_store(val + vv[n], g_Qvh, g_Qvl, idx);
                } else if (seg == 1) {
                    const size_t idx = (((size_t)(nb * NH + h)) * TT + t) * DH + dh;
                    split_store(val, g_Kh, g_Kl, idx);
                } else {
                    const size_t idx = ((size_t)(nb * NH + h) * DH + dh) * TT + t;
                    split_store(val, g_Vh, g_Vl, idx);
                }
            }
}

// ---------------------------------------------------------------------------
// Generic GEMM for R-proj (MODE 3), out-proj (MODE 4), attn@V (MODE 5).
// ---------------------------------------------------------------------------
template<int MODE, int BN, int WN, bool MG>
__global__ __launch_bounds__(256, 2) void mma_gemm(
    const bf16* __restrict__ Ah, const bf16* __restrict__ Al,
    const bf16* __restrict__ Bh, const bf16* __restrict__ Bl,
    const float* __restrict__ bias,
    float* __restrict__ o0,
    bf16* __restrict__ oh, bf16* __restrict__ ol, int M)
{
    constexpr int NN = WN / 8;
    const int m0 = blockIdx.x * 128, n0 = blockIdx.y * BN;
    size_t abase = 0, bbase = 0;
    if (MODE == 5) { abase = (size_t)blockIdx.z << 20; bbase = (size_t)blockIdx.z << 16; }

    float acc[2][NN][4] = {};
    mainloop<BN, NN, MG>(Ah, Al, Bh, Bl, abase, bbase, m0, n0, M, acc);

    const int lane = threadIdx.x & 31;
    const int w = threadIdx.x >> 5;
    const int wm = w & 3, wn = w >> 2;
    #pragma unroll
    for (int mi = 0; mi < 2; mi++)
        #pragma unroll
        for (int ni = 0; ni < NN; ni++)
            #pragma unroll
            for (int r4 = 0; r4 < 4; r4++) {
                const int m = m0 + wm * 32 + mi * 16 + (lane >> 2) + ((r4 & 2) ? 8 : 0);
                const int n = n0 + wn * WN + ni * 8 + ((lane & 3) << 1) + (r4 & 1);
                float val = acc[mi][ni][r4];
                if (MODE == 3) {
                    if (m < M) split_store(val, oh, ol, (size_t)m * 1024 + n);
                } else if (MODE == 4) {
                    o0[(size_t)m * 1024 + n] = val + bias[n];
                } else {   // MODE 5
                    const int bh = blockIdx.z;
                    const int nb = bh >> 4, h = bh & 15;
                    split_store(val, oh, ol, ((size_t)nb * 1024 + m) * 1024 + h * 64 + n);
                }
            }
}

// ---------------------------------------------------------------------------
// Tensor-core score kernel with rel-shift fused via fragment scatter.
// ---------------------------------------------------------------------------
#define SMEM_SCORE 107520
__global__ __launch_bounds__(256, 2) void score_mma_kernel()
{
    extern __shared__ char smemc[];
    float* Ss = (float*)smemc;                      // [64][132]
    bf16* A0 = (bf16*)(smemc + 33792);              // plane stride 4608 (64x72)
    bf16* B0 = (bf16*)(smemc + 52224);              // p1 stride 13824 ; p2 9216

    const int tid = threadIdx.x;
    const int w = tid >> 5, lane = tid & 31;
    const int wm = w & 1, wn = w >> 1;              // 2 x 4 warps
    const int j0 = blockIdx.x * 128;
    const int i0 = blockIdx.y * 64;
    const int bh = blockIdx.z;
    const int h  = bh & 15;
    const int rb0 = i0 - j0 + 896;

    {
        const bf16* Qvp[2] = {g_Qvh, g_Qvl};
        #pragma unroll
        for (int p = 0; p < 2; p++)
            #pragma unroll
            for (int it = 0; it < 2; it++) {
                int id = tid + it * 256;
                int r = id >> 3, c8 = id & 7;
                *(uint4*)(A0 + p * 4608 + r * 72 + c8 * 8) =
                    *(const uint4*)(Qvp[p] + ((size_t)bh * 1024 + i0 + r) * 64 + c8 * 8);
            }
        const bf16* Rp[2] = {g_Rh, g_Rl};
        #pragma unroll
        for (int p = 0; p < 2; p++)
            #pragma unroll
            for (int it = 0; it < 6; it++) {
                int id = tid + it * 256;
                int r = id >> 3, c8 = id & 7;
                int grow = rb0 + r; if (grow > 2046) grow = 2046;
                *(uint4*)(B0 + p * 13824 + r * 72 + c8 * 8) =
                    *(const uint4*)(Rp[p] + (size_t)grow * 1024 + h * 64 + c8 * 8);
            }
    }
    __syncthreads();

    {
        float acc[2][6][4] = {};
        #pragma unroll
        for (int ks = 0; ks < 64; ks += 16) {
            uint32_t a[2][2][4];
            #pragma unroll
            for (int p = 0; p < 2; p++)
                #pragma unroll
                for (int mi = 0; mi < 2; mi++)
                    ldsm4(a[p][mi], smem_u32(A0 + p * 4608 +
                        (wm * 32 + mi * 16 + (lane & 15)) * 72 + ks + ((lane >> 4) << 3)));
            uint32_t b[2][6][2];
            #pragma unroll
            for (int p = 0; p < 2; p++)
                #pragma unroll
                for (int pr = 0; pr < 3; pr++) {
                    uint32_t t4[4];
                    ldsm4(t4, smem_u32(B0 + p * 13824 +
                        (wn * 48 + pr * 16 + (lane & 7) + ((lane >> 4) << 3)) * 72 +
                        ks + (((lane >> 3) & 1) << 3)));
                    b[p][2 * pr    ][0] = t4[0]; b[p][2 * pr    ][1] = t4[1];
                    b[p][2 * pr + 1][0] = t4[2]; b[p][2 * pr + 1][1] = t4[3];
                }
            #pragma unroll
            for (int mi = 0; mi < 2; mi++)
                #pragma unroll
                for (int ni = 0; ni < 6; ni++) {
                    mma16816(acc[mi][ni], a[0][mi], b[0][ni]);
                    mma16816(acc[mi][ni], a[0][mi], b[1][ni]);
                    mma16816(acc[mi][ni], a[1][mi], b[0][ni]);
                }
        }
        #pragma unroll
        for (int mi = 0; mi < 2; mi++)
            #pragma unroll
            for (int ni = 0; ni < 6; ni++)
                #pragma unroll
                for (int r4 = 0; r4 < 4; r4++) {
                    const int il = wm * 32 + mi * 16 + (lane >> 2) + ((r4 & 2) ? 8 : 0);
                    const int rl = wn * 48 + ni * 8 + ((lane & 3) << 1) + (r4 & 1);
                    const int jl = il - rl + 127;
                    if (jl >= 0 && jl < 128) Ss[il * 132 + jl] = acc[mi][ni][r4];
                }
    }
    __syncthreads();

    {
        const bf16* Qup[2] = {g_Quh, g_Qul};
        #pragma unroll
        for (int p = 0; p < 2; p++)
            #pragma unroll
            for (int it = 0; it < 2; it++) {
                int id = tid + it * 256;
                int r = id >> 3, c8 = id & 7;
                *(uint4*)(A0 + p * 4608 + r * 72 + c8 * 8) =
                    *(const uint4*)(Qup[p] + ((size_t)bh * 1024 + i0 + r) * 64 + c8 * 8);
            }
        const bf16* Kp[2] = {g_Kh, g_Kl};
        #pragma unroll
        for (int p = 0; p < 2; p++)
            #pragma unroll
            for (int it = 0; it < 4; it++) {
                int id = tid + it * 256;
                int r = id >> 3, c8 = id & 7;
                *(uint4*)(B0 + p * 9216 + r * 72 + c8 * 8) =
                    *(const uint4*)(Kp[p] + ((size_t)bh * 1024 + j0 + r) * 64 + c8 * 8);
            }
    }
    __syncthreads();

    {
        float acc[2][4][4] = {};
        #pragma unroll
        for (int ks = 0; ks < 64; ks += 16) {
            uint32_t a[2][2][4];
            #pragma unroll
            for (int p = 0; p < 2; p++)
                #pragma unroll
                for (int mi = 0; mi < 2; mi++)
                    ldsm4(a[p][mi], smem_u32(A0 + p * 4608 +
                        (wm * 32 + mi * 16 + (lane & 15)) * 72 + ks + ((lane >> 4) << 3)));
            uint32_t b[2][4][2];
            #pragma unroll
            for (int p = 0; p < 2; p++)
                #pragma unroll
                for (int pr = 0; pr < 2; pr++) {
                    uint32_t t4[4];
                    ldsm4(t4, smem_u32(B0 + p * 9216 +
                        (wn * 32 + pr * 16 + (lane & 7) + ((lane >> 4) << 3)) * 72 +
                        ks + (((lane >> 3) & 1) << 3)));
                    b[p][2 * pr    ][0] = t4[0]; b[p][2 * pr    ][1] = t4[1];
                    b[p][2 * pr + 1][0] = t4[2]; b[p][2 * pr + 1][1] = t4[3];
                }
            #pragma unroll
            for (int mi = 0; mi < 2; mi++)
                #pragma unroll
                for (int ni = 0; ni < 4; ni++) {
                    mma16816(acc[mi][ni], a[0][mi], b[0][ni]);
                    mma16816(acc[mi][ni], a[0][mi], b[1][ni]);
                    mma16816(acc[mi][ni], a[1][mi], b[0][ni]);
                }
        }
        float* Sp = g_S + ((size_t)bh << 20);
        #pragma unroll
        for (int mi = 0; mi < 2; mi++)
            #pragma unroll
            for (int ni = 0; ni < 4; ni++)
                #pragma unroll
                for (int r4 = 0; r4 < 4; r4++) {
                    const int il = wm * 32 + mi * 16 + (lane >> 2) + ((r4 & 2) ? 8 : 0);
                    const int jl = wn * 32 + ni * 8 + ((lane & 3) << 1) + (r4 & 1);
                    Sp[(size_t)(i0 + il) * 1024 + j0 + jl] =
                        acc[mi][ni][r4] + Ss[il * 132 + jl];
                }
    }
}

// ---------------------------------------------------------------------------
// Row softmax: float4 loads, shuffle reductions, bf162-packed plane stores.
// ---------------------------------------------------------------------------
__global__ __launch_bounds__(256) void softmax_kernel()
{
    const int row = blockIdx.x;
    const int tid = threadIdx.x;    // 256
    const float4* p4 = (const float4*)(g_S + (size_t)row * TT);
    float4 v = p4[tid];
    v.x *= 0.125f; v.y *= 0.125f; v.z *= 0.125f; v.w *= 0.125f;

    float m = fmaxf(fmaxf(v.x, v.y), fmaxf(v.z, v.w));
    #pragma unroll
    for (int o = 16; o; o >>= 1) m = fmaxf(m, __shfl_xor_sync(0xffffffffu, m, o));
    __shared__ float wm_[8], ws_[8];
    if ((tid & 31) == 0) wm_[tid >> 5] = m;
    __syncthreads();
    float mm = wm_[0];
    #pragma unroll
    for (int i = 1; i < 8; i++) mm = fmaxf(mm, wm_[i]);

    v.x = expf(v.x - mm); v.y = expf(v.y - mm);
    v.z = expf(v.z - mm); v.w = expf(v.w - mm);
    float s = v.x + v.y + v.z + v.w;
    #pragma unroll
    for (int o = 16; o; o >>= 1) s += __shfl_xor_sync(0xffffffffu, s, o);
    if ((tid & 31) == 0) ws_[tid >> 5] = s;
    __syncthreads();
    float sum = ws_[0];
    #pragma unroll
    for (int i = 1; i < 8; i++) sum += ws_[i];
    const float inv = 1.f / sum;

    float pv[4] = {v.x * inv, v.y * inv, v.z * inv, v.w * inv};
    bf16 hv[4], lv[4];
    #pragma unroll
    for (int q = 0; q < 4; q++) {
        hv[q] = __float2bfloat16(pv[q]);
        lv[q] = __float2bfloat16(pv[q] - __bfloat162float(hv[q]));
    }
    __nv_bfloat162* ph2 = (__nv_bfloat162*)(g_Ph + (size_t)row * TT);
    __nv_bfloat162* pl2 = (__nv_bfloat162*)(g_Pl + (size_t)row * TT);
    ph2[tid * 2 + 0] = __nv_bfloat162(hv[0], hv[1]);
    ph2[tid * 2 + 1] = __nv_bfloat162(hv[2], hv[3]);
    pl2[tid * 2 + 0] = __nv_bfloat162(lv[0], lv[1]);
    pl2[tid * 2 + 1] = __nv_bfloat162(lv[2], lv[3]);
}

// ---------------------------------------------------------------------------
extern "C" void kernel_launch(void* const* d_in, const int* in_sizes, int n_in,
                              void* d_out, int out_size)
{
    (void)in_sizes; (void)n_in; (void)out_size;
    const float* x      = (const float*)d_in[0];
    const float* rel_pe = (const float*)d_in[1];
    const float* Wq     = (const float*)d_in[2];
    const float* bq     = (const float*)d_in[3];
    const float* Wk     = (const float*)d_in[4];
    const float* bk     = (const float*)d_in[5];
    const float* Wv     = (const float*)d_in[6];
    const float* bv     = (const float*)d_in[7];
    const float* Wo     = (const float*)d_in[8];
    const float* bo     = (const float*)d_in[9];
    const float* Wr     = (const float*)d_in[10];
    const float* u      = (const float*)d_in[11];
    const float* v      = (const float*)d_in[12];
    float* out = (float*)d_out;

    bf16 *pxh, *pxl, *prh, *prl, *pwrh, *pwrl, *pwoh, *pwol;
    bf16 *pRh, *pRl, *pVh, *pVl, *pPh, *pPl, *pOh, *pOl;
    cudaGetSymbolAddress((void**)&pxh, g_xh);  cudaGetSymbolAddress((void**)&pxl, g_xl);
    cudaGetSymbolAddress((void**)&prh, g_rph); cudaGetSymbolAddress((void**)&prl, g_rpl);
    cudaGetSymbolAddress((void**)&pwrh, g_wrh); cudaGetSymbolAddress((void**)&pwrl, g_wrl);
    cudaGetSymbolAddress((void**)&pwoh, g_woh); cudaGetSymbolAddress((void**)&pwol, g_wol);
    cudaGetSymbolAddress((void**)&pRh, g_Rh);  cudaGetSymbolAddress((void**)&pRl, g_Rl);
    cudaGetSymbolAddress((void**)&pVh, g_Vh);  cudaGetSymbolAddress((void**)&pVl, g_Vl);
    cudaGetSymbolAddress((void**)&pPh, g_Ph);  cudaGetSymbolAddress((void**)&pPl, g_Pl);
    cudaGetSymbolAddress((void**)&pOh, g_Oh);  cudaGetSymbolAddress((void**)&pOl, g_Ol);

    const int SMEM_G128 = 2 * 2 * 128 * 40 * 2 * 2;   // 81920 B
    const int SMEM_G64  = 2 * 2 * 128 * 40 * 2 + 2 * 2 * 64 * 40 * 2; // 61440 B
    cudaFuncSetAttribute((const void*)qkv_gemm,
                         cudaFuncAttributeMaxDynamicSharedMemorySize, SMEM_G128);
    cudaFuncSetAttribute((const void*)mma_gemm<3,128,64,true>,
                         cudaFuncAttributeMaxDynamicSharedMemorySize, SMEM_G128);
    cudaFuncSetAttribute((const void*)mma_gemm<4,128,64,false>,
                         cudaFuncAttributeMaxDynamicSharedMemorySize, SMEM_G128);
    cudaFuncSetAttribute((const void*)mma_gemm<5,64,32,false>,
                         cudaFuncAttributeMaxDynamicSharedMemorySize, SMEM_G64);
    cudaFuncSetAttribute((const void*)score_mma_kernel,
                         cudaFuncAttributeMaxDynamicSharedMemorySize, SMEM_SCORE);

    const int NX = NB * TT * DM;
    const int NR = RLEN * DM;
    const int NW = DM * DM;

    // slot 4 = fused QKV GEMM (the profiled launch)
    split_kernel<<<(NX + 255) / 256, 256>>>(x, pxh, pxl, NX);              // 1
    split3_kernel<<<(3 * NW + 255) / 256, 256>>>(Wq, Wk, Wv);              // 2
    split_kernel<<<(NR + 255) / 256, 256>>>(rel_pe, prh, prl, NR);         // 3
    qkv_gemm<<<dim3(32, 24), 256, SMEM_G128>>>(bq, bk, bv, u, v);          // 4 (profiled)

    split_kernel<<<(NW + 255) / 256, 256>>>(Wr, pwrh, pwrl, NW);
    split_kernel<<<(NW + 255) / 256, 256>>>(Wo, pwoh, pwol, NW);

    mma_gemm<3, 128, 64, true><<<dim3(16, 8), 256, SMEM_G128>>>(
        prh, prl, pwrh, pwrl, nullptr, nullptr, pRh, pRl, RLEN);

    score_mma_kernel<<<dim3(TT / 128, TT / 64, NB * NH), 256, SMEM_SCORE>>>();

    softmax_kernel<<<NB * NH * TT, 256>>>();

    mma_gemm<5, 64, 32, false><<<dim3(8, 1, NB * NH), 256, SMEM_G64>>>(
        pPh, pPl, pVh, pVl, nullptr, nullptr, pOh, pOl, TT);

    mma_gemm<4, 128, 64, false><<<dim3(32, 8), 256, SMEM_G128>>>(
        pOh, pOl, pwoh, pwol, bo, out, nullptr, nullptr, NB * TT);
}